// round 1
// baseline (speedup 1.0000x reference)
#include <cuda_runtime.h>
#include <cuda_bf16.h>
#include <math.h>

// Problem constants
#define Bn 4
#define Cc 512
#define Hh 56
#define Ww 56
#define Gg 16
#define Pp 9
#define GC 32
#define HW 3136          // 56*56
#define Mtot 12544       // B*H*W
#define Noff 288         // G*P*2
#define Nmsk 144         // G*P
#define Ncat 432         // Noff+Nmsk

// ---------------- scratch (device globals; no allocation allowed) ----------
__device__ float g_xh[Mtot * Cc];     // NHWC input
__device__ float g_xp[Mtot * Cc];     // input_proj output
__device__ float g_x1[Mtot * Cc];     // dw+LN+GELU branch
__device__ float g_om[Mtot * Ncat];   // [offset(288) | mask(144)] per pixel
__device__ float g_ys[Mtot * Cc];     // DCN sampled output (NHWC)
__device__ float g_wcat[Cc * Ncat];   // concat [w_off | w_mask]
__device__ float g_bcat[Ncat];

// ---------------- NCHW -> NHWC transpose -----------------------------------
__global__ __launch_bounds__(256)
void nchw_to_nhwc(const float* __restrict__ x, float* __restrict__ xh) {
    __shared__ float tile[32][33];
    const int bb = blockIdx.z;
    const int hw0 = blockIdx.x * 32;
    const int c0 = blockIdx.y * 32;
    const int tx = threadIdx.x;   // 32
    const int ty = threadIdx.y;   // 8
    const float* xb = x + (size_t)bb * Cc * HW;
    #pragma unroll
    for (int i = 0; i < 32; i += 8)
        tile[ty + i][tx] = xb[(size_t)(c0 + ty + i) * HW + hw0 + tx];
    __syncthreads();
    float* xhb = xh + (size_t)bb * HW * Cc;
    #pragma unroll
    for (int i = 0; i < 32; i += 8)
        xhb[(size_t)(hw0 + ty + i) * Cc + c0 + tx] = tile[tx][ty + i];
}

// ---------------- generic SGEMM: C = A[M,K] @ B[K,N] + bias ----------------
// 128x128 tile, BK=8, 256 threads, 8x8 per thread.
__global__ __launch_bounds__(256)
void sgemm_bias(const float* __restrict__ A, const float* __restrict__ B,
                const float* __restrict__ bias, float* __restrict__ C,
                int M, int N, int K) {
    __shared__ float As[8][128];
    __shared__ float Bs[8][128];
    const int tid = threadIdx.x;
    const int tx = tid & 15;
    const int ty = tid >> 4;
    const int bm = blockIdx.y * 128;
    const int bn = blockIdx.x * 128;

    float acc[8][8];
    #pragma unroll
    for (int i = 0; i < 8; i++)
        #pragma unroll
        for (int j = 0; j < 8; j++) acc[i][j] = 0.f;

    const int ar = tid >> 1;          // 0..127 (A row within tile)
    const int ak = (tid & 1) << 2;    // 0 or 4  (k offset)
    const int kb = tid >> 5;          // 0..7    (B k row)
    const int cb = (tid & 31) << 2;   // 0..124  (B col offset)
    const float* Ap = A + (size_t)(bm + ar) * K + ak;
    const int gcol = bn + cb;

    for (int k0 = 0; k0 < K; k0 += 8) {
        float4 av = *(const float4*)(Ap + k0);
        float4 bv = make_float4(0.f, 0.f, 0.f, 0.f);
        if (gcol < N) bv = *(const float4*)(B + (size_t)(k0 + kb) * N + gcol);
        __syncthreads();
        As[ak + 0][ar] = av.x; As[ak + 1][ar] = av.y;
        As[ak + 2][ar] = av.z; As[ak + 3][ar] = av.w;
        *(float4*)&Bs[kb][cb] = bv;
        __syncthreads();
        #pragma unroll
        for (int kk = 0; kk < 8; kk++) {
            float4 a0 = *(const float4*)&As[kk][ty * 8];
            float4 a1 = *(const float4*)&As[kk][ty * 8 + 4];
            float4 b0 = *(const float4*)&Bs[kk][tx * 8];
            float4 b1 = *(const float4*)&Bs[kk][tx * 8 + 4];
            float a[8] = {a0.x, a0.y, a0.z, a0.w, a1.x, a1.y, a1.z, a1.w};
            float bb[8] = {b0.x, b0.y, b0.z, b0.w, b1.x, b1.y, b1.z, b1.w};
            #pragma unroll
            for (int i = 0; i < 8; i++)
                #pragma unroll
                for (int j = 0; j < 8; j++) acc[i][j] = fmaf(a[i], bb[j], acc[i][j]);
        }
    }
    #pragma unroll
    for (int i = 0; i < 8; i++) {
        const int row = bm + ty * 8 + i;
        #pragma unroll
        for (int j4 = 0; j4 < 8; j4 += 4) {
            const int col = bn + tx * 8 + j4;
            if (col < N) {
                float4 v;
                v.x = acc[i][j4 + 0] + bias[col + 0];
                v.y = acc[i][j4 + 1] + bias[col + 1];
                v.z = acc[i][j4 + 2] + bias[col + 2];
                v.w = acc[i][j4 + 3] + bias[col + 3];
                *(float4*)&C[(size_t)row * N + col] = v;
            }
        }
    }
}

// ---------------- output GEMM with BN+SiLU epilogue, NCHW store ------------
__global__ __launch_bounds__(256)
void sgemm_out(const float* __restrict__ A, const float* __restrict__ B,
               const float* __restrict__ b_out,
               const float* __restrict__ bn_g, const float* __restrict__ bn_b,
               const float* __restrict__ bn_m, const float* __restrict__ bn_v,
               float* __restrict__ out, int M, int N, int K) {
    __shared__ float As[8][128];
    __shared__ float Bs[8][128];
    const int tid = threadIdx.x;
    const int tx = tid & 15;
    const int ty = tid >> 4;
    const int bm = blockIdx.y * 128;
    const int bn = blockIdx.x * 128;

    float acc[8][8];
    #pragma unroll
    for (int i = 0; i < 8; i++)
        #pragma unroll
        for (int j = 0; j < 8; j++) acc[i][j] = 0.f;

    const int ar = tid >> 1;
    const int ak = (tid & 1) << 2;
    const int kb = tid >> 5;
    const int cb = (tid & 31) << 2;
    const float* Ap = A + (size_t)(bm + ar) * K + ak;
    const int gcol = bn + cb;

    for (int k0 = 0; k0 < K; k0 += 8) {
        float4 av = *(const float4*)(Ap + k0);
        float4 bv = *(const float4*)(B + (size_t)(k0 + kb) * N + gcol);
        __syncthreads();
        As[ak + 0][ar] = av.x; As[ak + 1][ar] = av.y;
        As[ak + 2][ar] = av.z; As[ak + 3][ar] = av.w;
        *(float4*)&Bs[kb][cb] = bv;
        __syncthreads();
        #pragma unroll
        for (int kk = 0; kk < 8; kk++) {
            float4 a0 = *(const float4*)&As[kk][ty * 8];
            float4 a1 = *(const float4*)&As[kk][ty * 8 + 4];
            float4 b0 = *(const float4*)&Bs[kk][tx * 8];
            float4 b1 = *(const float4*)&Bs[kk][tx * 8 + 4];
            float a[8] = {a0.x, a0.y, a0.z, a0.w, a1.x, a1.y, a1.z, a1.w};
            float bb[8] = {b0.x, b0.y, b0.z, b0.w, b1.x, b1.y, b1.z, b1.w};
            #pragma unroll
            for (int i = 0; i < 8; i++)
                #pragma unroll
                for (int j = 0; j < 8; j++) acc[i][j] = fmaf(a[i], bb[j], acc[i][j]);
        }
    }
    // per-column epilogue params
    float pb[8], pm[8], ps[8], pc[8];
    #pragma unroll
    for (int j = 0; j < 8; j++) {
        const int col = bn + tx * 8 + j;
        pb[j] = b_out[col];
        pm[j] = bn_m[col];
        ps[j] = bn_g[col] * rsqrtf(bn_v[col] + 1e-5f);
        pc[j] = bn_b[col];
    }
    #pragma unroll
    for (int i = 0; i < 8; i++) {
        const int row = bm + ty * 8 + i;
        const int bidx = row / HW;
        const int hw = row - bidx * HW;
        #pragma unroll
        for (int j = 0; j < 8; j++) {
            const int col = bn + tx * 8 + j;
            float yv = acc[i][j] + pb[j];
            yv = (yv - pm[j]) * ps[j] + pc[j];
            const float sv = yv / (1.0f + expf(-yv));
            out[((size_t)bidx * Cc + col) * HW + hw] = sv;
        }
    }
}

// ---------------- depthwise 3x3 + LayerNorm + exact GELU -------------------
__global__ __launch_bounds__(256)
void dw_ln_gelu(const float* __restrict__ xh, const float* __restrict__ wdw,
                const float* __restrict__ bdw, const float* __restrict__ lng,
                const float* __restrict__ lnb, float* __restrict__ x1) {
    __shared__ float sred[256];
    const int m = blockIdx.x;
    const int b = m / HW;
    const int hw = m - b * HW;
    const int h = hw / Ww;
    const int w = hw - h * Ww;
    const int tid = threadIdx.x;
    const int c = tid * 2;

    float a0 = 0.f, a1 = 0.f;
    #pragma unroll
    for (int ky = 0; ky < 3; ky++) {
        const int hy = h + ky - 1;
        if ((unsigned)hy >= (unsigned)Hh) continue;
        #pragma unroll
        for (int kx = 0; kx < 3; kx++) {
            const int wx = w + kx - 1;
            if ((unsigned)wx >= (unsigned)Ww) continue;
            const float2 v = *(const float2*)&xh[((size_t)(b * HW + hy * Ww + wx)) * Cc + c];
            const float2 wv = *(const float2*)&wdw[(ky * 3 + kx) * Cc + c];
            a0 = fmaf(v.x, wv.x, a0);
            a1 = fmaf(v.y, wv.y, a1);
        }
    }
    const float2 bb = *(const float2*)&bdw[c];
    a0 += bb.x; a1 += bb.y;

    // mean
    sred[tid] = a0 + a1;
    __syncthreads();
    for (int s = 128; s > 0; s >>= 1) {
        if (tid < s) sred[tid] += sred[tid + s];
        __syncthreads();
    }
    const float mu = sred[0] * (1.0f / 512.0f);
    __syncthreads();
    // variance (two-pass)
    const float d0 = a0 - mu, d1 = a1 - mu;
    sred[tid] = d0 * d0 + d1 * d1;
    __syncthreads();
    for (int s = 128; s > 0; s >>= 1) {
        if (tid < s) sred[tid] += sred[tid + s];
        __syncthreads();
    }
    const float var = sred[0] * (1.0f / 512.0f);
    const float rstd = rsqrtf(var + 1e-6f);

    const float2 gg = *(const float2*)&lng[c];
    const float2 be = *(const float2*)&lnb[c];
    float o0 = d0 * rstd * gg.x + be.x;
    float o1 = d1 * rstd * gg.y + be.y;
    o0 = 0.5f * o0 * (1.0f + erff(o0 * 0.7071067811865475f));
    o1 = 0.5f * o1 * (1.0f + erff(o1 * 0.7071067811865475f));
    *(float2*)&x1[(size_t)m * Cc + c] = make_float2(o0, o1);
}

// ---------------- concat offset/mask weights -------------------------------
__global__ __launch_bounds__(256)
void concat_w(const float* __restrict__ w_off, const float* __restrict__ b_off,
              const float* __restrict__ w_mask, const float* __restrict__ b_mask,
              float* __restrict__ wcat, float* __restrict__ bcat) {
    const int idx = blockIdx.x * 256 + threadIdx.x;
    if (idx < Cc * Ncat) {
        const int k = idx / Ncat;
        const int n = idx - k * Ncat;
        wcat[idx] = (n < Noff) ? w_off[k * Noff + n] : w_mask[k * Nmsk + (n - Noff)];
    }
    if (idx < Ncat) bcat[idx] = (idx < Noff) ? b_off[idx] : b_mask[idx - Noff];
}

// ---------------- softmax over P for mask logits (in place) ----------------
__global__ __launch_bounds__(256)
void softmax_mask(float* __restrict__ om) {
    const int idx = blockIdx.x * 256 + threadIdx.x;
    if (idx >= Mtot * Gg) return;
    const int m = idx >> 4;
    const int g = idx & 15;
    float* p = om + (size_t)m * Ncat + Noff + g * Pp;
    float v[Pp];
    float mx = -1e30f;
    #pragma unroll
    for (int i = 0; i < Pp; i++) { v[i] = p[i]; mx = fmaxf(mx, v[i]); }
    float s = 0.f;
    #pragma unroll
    for (int i = 0; i < Pp; i++) { v[i] = expf(v[i] - mx); s += v[i]; }
    const float inv = 1.0f / s;
    #pragma unroll
    for (int i = 0; i < Pp; i++) p[i] = v[i] * inv;
}

// ---------------- DCNv3 bilinear sampling core -----------------------------
// One warp per (pixel, group); lane = channel within group (GC==32).
__device__ __forceinline__ float dcn_fetch(const float* __restrict__ base,
                                           int yu, int xu) {
    if ((unsigned)yu < (unsigned)Hh && (unsigned)xu < (unsigned)Ww)
        return base[(size_t)(yu * Ww + xu) * Cc];
    return 0.f;
}

__global__ __launch_bounds__(256)
void dcn_sample(const float* __restrict__ xp, const float* __restrict__ om,
                float* __restrict__ ys) {
    const int gid = blockIdx.x * 8 + (threadIdx.x >> 5);
    const int lane = threadIdx.x & 31;
    if (gid >= Mtot * Gg) return;
    const int m = gid >> 4;
    const int g = gid & 15;
    const int b = m / HW;
    const int hw = m - b * HW;
    const int h = hw / Ww;
    const int w = hw - h * Ww;

    // reference points: (coord + 0.5 + 1) / 58
    const float rx = ((float)w + 1.5f) / 58.0f;
    const float ry = ((float)h + 1.5f) / 58.0f;

    const float* offp = om + (size_t)m * Ncat + g * (Pp * 2);
    const float* mskp = om + (size_t)m * Ncat + Noff + g * Pp;
    const float* base = xp + (size_t)b * HW * Cc + g * GC + lane;

    float acc = 0.f;
    #pragma unroll
    for (int p = 0; p < Pp; p++) {
        const int kx = p / 3;            // kx-major flattening
        const int ky = p - kx * 3;
        const float ox = offp[2 * p];
        const float oy = offp[2 * p + 1];
        // lx = (ref_x + gx) + off/Win ; px = lx*Win - 0.5 (reference order)
        const float lx = (rx + (float)(kx - 1) / 58.0f) + ox / 58.0f;
        const float ly = (ry + (float)(ky - 1) / 58.0f) + oy / 58.0f;
        const float px = lx * 58.0f - 0.5f;
        const float py = ly * 58.0f - 0.5f;
        const float x0f = floorf(px);
        const float y0f = floorf(py);
        const float txf = px - x0f;
        const float tyf = py - y0f;
        const int x0 = (int)x0f;         // padded coords
        const int y0 = (int)y0f;
        const float msk = mskp[p];
        // padded->unpadded: subtract PAD=1
        const float v00 = dcn_fetch(base, y0 - 1, x0 - 1);
        const float v01 = dcn_fetch(base, y0 - 1, x0);
        const float v10 = dcn_fetch(base, y0,     x0 - 1);
        const float v11 = dcn_fetch(base, y0,     x0);
        const float s = (1.f - tyf) * (1.f - txf) * v00
                      + (1.f - tyf) * txf * v01
                      + tyf * (1.f - txf) * v10
                      + tyf * txf * v11;
        acc = fmaf(msk, s, acc);
    }
    ys[(size_t)m * Cc + g * GC + lane] = acc;
}

// ---------------- host launch ----------------------------------------------
extern "C" void kernel_launch(void* const* d_in, const int* in_sizes, int n_in,
                              void* d_out, int out_size) {
    const float* x      = (const float*)d_in[0];
    const float* w_in   = (const float*)d_in[1];
    const float* b_in   = (const float*)d_in[2];
    const float* w_dw   = (const float*)d_in[3];
    const float* b_dw   = (const float*)d_in[4];
    const float* ln_g   = (const float*)d_in[5];
    const float* ln_b   = (const float*)d_in[6];
    const float* w_off  = (const float*)d_in[7];
    const float* b_off  = (const float*)d_in[8];
    const float* w_mask = (const float*)d_in[9];
    const float* b_mask = (const float*)d_in[10];
    const float* w_out  = (const float*)d_in[11];
    const float* b_out  = (const float*)d_in[12];
    const float* bn_g   = (const float*)d_in[13];
    const float* bn_b   = (const float*)d_in[14];
    const float* bn_m   = (const float*)d_in[15];
    const float* bn_v   = (const float*)d_in[16];

    float *xh, *xp, *x1, *om, *ys, *wcat, *bcat;
    cudaGetSymbolAddress((void**)&xh, g_xh);
    cudaGetSymbolAddress((void**)&xp, g_xp);
    cudaGetSymbolAddress((void**)&x1, g_x1);
    cudaGetSymbolAddress((void**)&om, g_om);
    cudaGetSymbolAddress((void**)&ys, g_ys);
    cudaGetSymbolAddress((void**)&wcat, g_wcat);
    cudaGetSymbolAddress((void**)&bcat, g_bcat);

    // 1. NCHW -> NHWC
    nchw_to_nhwc<<<dim3(HW / 32, Cc / 32, Bn), dim3(32, 8)>>>(x, xh);
    // 2. input_proj: xp = xh @ w_in + b_in
    sgemm_bias<<<dim3(Cc / 128, Mtot / 128), 256>>>(xh, w_in, b_in, xp,
                                                    Mtot, Cc, Cc);
    // 3. depthwise + LN + GELU
    dw_ln_gelu<<<Mtot, 256>>>(xh, w_dw, b_dw, ln_g, ln_b, x1);
    // 4. concat offset/mask weights
    concat_w<<<(Cc * Ncat + 255) / 256, 256>>>(w_off, b_off, w_mask, b_mask,
                                               wcat, bcat);
    // 5. offset/mask GEMM: om = x1 @ wcat + bcat
    sgemm_bias<<<dim3((Ncat + 127) / 128, Mtot / 128), 256>>>(x1, wcat, bcat, om,
                                                              Mtot, Ncat, Cc);
    // 6. softmax over P (in place on mask part)
    softmax_mask<<<(Mtot * Gg + 255) / 256, 256>>>(om);
    // 7. DCN sampling
    dcn_sample<<<(Mtot * Gg) / 8, 256>>>(xp, om, ys);
    // 8. output_proj + BN + SiLU, NCHW store
    sgemm_out<<<dim3(Cc / 128, Mtot / 128), 256>>>(ys, w_out, b_out,
                                                   bn_g, bn_b, bn_m, bn_v,
                                                   (float*)d_out, Mtot, Cc, Cc);
}

// round 5
// speedup vs baseline: 1.3936x; 1.3936x over previous
#include <cuda_runtime.h>
#include <cuda_bf16.h>
#include <math.h>
#include <cstdint>

typedef unsigned int u32;

// Problem constants
#define Bn 4
#define Cc 512
#define Hh 56
#define Ww 56
#define Gg 16
#define Pp 9
#define GC 32
#define HW 3136          // 56*56
#define Mtot 12544       // B*H*W
#define Noff 288         // G*P*2
#define Nmsk 144         // G*P
#define Ncat 432         // Noff+Nmsk

// ---------------- scratch (device globals; no allocation allowed) ----------
__device__ float g_xh[Mtot * Cc];     // NHWC input
__device__ float g_xp[Mtot * Cc];     // input_proj output
__device__ float g_x1[Mtot * Cc];     // dw+LN+GELU branch
__device__ float g_om[Mtot * Ncat];   // [offset(288) | mask(144)] per pixel
__device__ float g_ys[Mtot * Cc];     // DCN sampled output (NHWC)
__device__ float g_wcat[Cc * Ncat];   // concat [w_off | w_mask]
__device__ float g_bcat[Ncat];

// ---------------- NCHW -> NHWC transpose -----------------------------------
__global__ __launch_bounds__(256)
void nchw_to_nhwc(const float* __restrict__ x) {
    __shared__ float tile[32][33];
    const int bb = blockIdx.z;
    const int hw0 = blockIdx.x * 32;
    const int c0 = blockIdx.y * 32;
    const int tx = threadIdx.x;   // 32
    const int ty = threadIdx.y;   // 8
    const float* xb = x + (size_t)bb * Cc * HW;
    #pragma unroll
    for (int i = 0; i < 32; i += 8)
        tile[ty + i][tx] = xb[(size_t)(c0 + ty + i) * HW + hw0 + tx];
    __syncthreads();
    float* xhb = g_xh + (size_t)bb * HW * Cc;
    #pragma unroll
    for (int i = 0; i < 32; i += 8)
        xhb[(size_t)(hw0 + ty + i) * Cc + c0 + tx] = tile[tx][ty + i];
}

// ---------------- tensor-core GEMM pieces (split-bf16, 3 MMA passes) -------
__device__ __forceinline__ void ldmA4(u32* r, u32 addr) {
    asm volatile("ldmatrix.sync.aligned.m8n8.x4.shared.b16 {%0,%1,%2,%3}, [%4];\n"
                 : "=r"(r[0]), "=r"(r[1]), "=r"(r[2]), "=r"(r[3]) : "r"(addr));
}
__device__ __forceinline__ void ldmB2(u32* r, u32 addr) {
    asm volatile("ldmatrix.sync.aligned.m8n8.x2.trans.shared.b16 {%0,%1}, [%2];\n"
                 : "=r"(r[0]), "=r"(r[1]) : "r"(addr));
}
__device__ __forceinline__ void mma16816(float* c, const u32* a, const u32* b) {
    asm volatile("mma.sync.aligned.m16n8k16.row.col.f32.bf16.bf16.f32 "
                 "{%0,%1,%2,%3}, {%4,%5,%6,%7}, {%8,%9}, {%0,%1,%2,%3};\n"
                 : "+f"(c[0]), "+f"(c[1]), "+f"(c[2]), "+f"(c[3])
                 : "r"(a[0]), "r"(a[1]), "r"(a[2]), "r"(a[3]), "r"(b[0]), "r"(b[1]));
}
__device__ __forceinline__ void split2u(float v, unsigned short& h, unsigned short& l) {
    const __nv_bfloat16 hh = __float2bfloat16_rn(v);
    const float r = v - __bfloat162float(hh);
    h = __bfloat16_as_ushort(hh);
    l = __bfloat16_as_ushort(__float2bfloat16_rn(r));
}

// Main-loop core: computes acc[2][8][4] for this thread's warp tile.
// A is [M,K] row-major, B is [K,N] row-major. Smem passed from caller.
__device__ __forceinline__ void gemm_core(
    const float* __restrict__ A, const float* __restrict__ B,
    int N, int K, int bm, int bn,
    unsigned short (*Ash)[40], unsigned short (*Asl)[40],
    unsigned short (*Bsh)[136], unsigned short (*Bsl)[136],
    float acc[2][8][4]) {
    const int tid = threadIdx.x;
    const int arow = tid >> 1;                 // 0..127
    const int acb = (tid & 1) * 16;            // 0 / 16
    const int brow = tid >> 3;                 // 0..31
    const int bcb = (tid & 7) * 16;            // 0..112
    const float* Ap = A + (size_t)(bm + arow) * K + acb;
    const float* Bp = B + (size_t)brow * N + bn + bcb;
    const float4 z4 = make_float4(0.f, 0.f, 0.f, 0.f);

    float4 av[4], bv[4];
    #pragma unroll
    for (int i = 0; i < 4; i++) av[i] = *(const float4*)(Ap + i * 4);
    #pragma unroll
    for (int i = 0; i < 4; i++) {
        const int c = bn + bcb + i * 4;
        bv[i] = (c < N) ? *(const float4*)(Bp + i * 4) : z4;
    }
    #pragma unroll
    for (int i = 0; i < 4; i++) {
        float vv[4]; vv[0] = av[i].x; vv[1] = av[i].y; vv[2] = av[i].z; vv[3] = av[i].w;
        #pragma unroll
        for (int j = 0; j < 4; j++)
            split2u(vv[j], Ash[arow][acb + i * 4 + j], Asl[arow][acb + i * 4 + j]);
        float wv[4]; wv[0] = bv[i].x; wv[1] = bv[i].y; wv[2] = bv[i].z; wv[3] = bv[i].w;
        #pragma unroll
        for (int j = 0; j < 4; j++)
            split2u(wv[j], Bsh[brow][bcb + i * 4 + j], Bsl[brow][bcb + i * 4 + j]);
    }
    __syncthreads();

    const int wid = tid >> 5;
    const int lane = tid & 31;
    const int wm = (wid >> 1) * 32;   // 0,32,64,96
    const int wn = (wid & 1) * 64;    // 0,64
    const int arow16 = lane & 15;
    const int akoff = (lane >> 4) * 8;
    const u32 sAh = (u32)__cvta_generic_to_shared(&Ash[0][0]);
    const u32 sAl = (u32)__cvta_generic_to_shared(&Asl[0][0]);
    const u32 sBh = (u32)__cvta_generic_to_shared(&Bsh[0][0]);
    const u32 sBl = (u32)__cvta_generic_to_shared(&Bsl[0][0]);

    for (int k0 = 32;; k0 += 32) {
        const bool more = (k0 < K);
        if (more) {
            #pragma unroll
            for (int i = 0; i < 4; i++) av[i] = *(const float4*)(Ap + k0 + i * 4);
            #pragma unroll
            for (int i = 0; i < 4; i++) {
                const int c = bn + bcb + i * 4;
                bv[i] = (c < N) ? *(const float4*)(Bp + (size_t)k0 * N + i * 4) : z4;
            }
        }
        #pragma unroll
        for (int ks = 0; ks < 32; ks += 16) {
            u32 aH[2][4], aL[2][4];
            #pragma unroll
            for (int mt = 0; mt < 2; mt++) {
                const u32 off = (u32)(((wm + mt * 16 + arow16) * 40 + ks + akoff) * 2);
                ldmA4(aH[mt], sAh + off);
                ldmA4(aL[mt], sAl + off);
            }
            u32 bH[8][2], bL[8][2];
            #pragma unroll
            for (int nt = 0; nt < 8; nt++) {
                const u32 off = (u32)(((ks + arow16) * 136 + wn + nt * 8) * 2);
                ldmB2(bH[nt], sBh + off);
                ldmB2(bL[nt], sBl + off);
            }
            #pragma unroll
            for (int mt = 0; mt < 2; mt++) {
                #pragma unroll
                for (int nt = 0; nt < 8; nt++) {
                    mma16816(acc[mt][nt], aH[mt], bH[nt]);
                    mma16816(acc[mt][nt], aH[mt], bL[nt]);
                    mma16816(acc[mt][nt], aL[mt], bH[nt]);
                }
            }
        }
        if (!more) break;
        __syncthreads();
        #pragma unroll
        for (int i = 0; i < 4; i++) {
            float vv[4]; vv[0] = av[i].x; vv[1] = av[i].y; vv[2] = av[i].z; vv[3] = av[i].w;
            #pragma unroll
            for (int j = 0; j < 4; j++)
                split2u(vv[j], Ash[arow][acb + i * 4 + j], Asl[arow][acb + i * 4 + j]);
            float wv[4]; wv[0] = bv[i].x; wv[1] = bv[i].y; wv[2] = bv[i].z; wv[3] = bv[i].w;
            #pragma unroll
            for (int j = 0; j < 4; j++)
                split2u(wv[j], Bsh[brow][bcb + i * 4 + j], Bsl[brow][bcb + i * 4 + j]);
        }
        __syncthreads();
    }
}

// ---- GEMM 1: g_xp = g_xh @ w_in + b_in  (M=12544, N=512, K=512) -----------
__global__ __launch_bounds__(256, 1)
void gemm_in(const float* __restrict__ Bw, const float* __restrict__ bias) {
    __shared__ unsigned short Ash[128][40];
    __shared__ unsigned short Asl[128][40];
    __shared__ unsigned short Bsh[32][136];
    __shared__ unsigned short Bsl[32][136];
    float acc[2][8][4];
    #pragma unroll
    for (int i = 0; i < 2; i++)
        #pragma unroll
        for (int j = 0; j < 8; j++)
            #pragma unroll
            for (int q = 0; q < 4; q++) acc[i][j][q] = 0.f;
    const int bm = blockIdx.y * 128;
    const int bnn = blockIdx.x * 128;
    gemm_core(g_xh, Bw, Cc, Cc, bm, bnn, Ash, Asl, Bsh, Bsl, acc);

    const int wid = threadIdx.x >> 5;
    const int lane = threadIdx.x & 31;
    const int wm = (wid >> 1) * 32;
    const int wn = (wid & 1) * 64;
    const int r0 = lane >> 2;
    const int c0 = (lane & 3) * 2;
    #pragma unroll
    for (int mt = 0; mt < 2; mt++) {
        #pragma unroll
        for (int nt = 0; nt < 8; nt++) {
            const int col = bnn + wn + nt * 8 + c0;
            #pragma unroll
            for (int half = 0; half < 2; half++) {
                const int row = bm + wm + mt * 16 + r0 + half * 8;
                g_xp[(size_t)row * Cc + col]     = acc[mt][nt][half * 2 + 0] + bias[col];
                g_xp[(size_t)row * Cc + col + 1] = acc[mt][nt][half * 2 + 1] + bias[col + 1];
            }
        }
    }
}

// ---- GEMM 2: g_om = g_x1 @ g_wcat + g_bcat  (N=432, K=512) ----------------
__global__ __launch_bounds__(256, 1)
void gemm_om() {
    __shared__ unsigned short Ash[128][40];
    __shared__ unsigned short Asl[128][40];
    __shared__ unsigned short Bsh[32][136];
    __shared__ unsigned short Bsl[32][136];
    float acc[2][8][4];
    #pragma unroll
    for (int i = 0; i < 2; i++)
        #pragma unroll
        for (int j = 0; j < 8; j++)
            #pragma unroll
            for (int q = 0; q < 4; q++) acc[i][j][q] = 0.f;
    const int bm = blockIdx.y * 128;
    const int bnn = blockIdx.x * 128;
    gemm_core(g_x1, g_wcat, Ncat, Cc, bm, bnn, Ash, Asl, Bsh, Bsl, acc);

    const int wid = threadIdx.x >> 5;
    const int lane = threadIdx.x & 31;
    const int wm = (wid >> 1) * 32;
    const int wn = (wid & 1) * 64;
    const int r0 = lane >> 2;
    const int c0 = (lane & 3) * 2;
    #pragma unroll
    for (int mt = 0; mt < 2; mt++) {
        #pragma unroll
        for (int nt = 0; nt < 8; nt++) {
            const int col = bnn + wn + nt * 8 + c0;
            if (col < Ncat) {
                #pragma unroll
                for (int half = 0; half < 2; half++) {
                    const int row = bm + wm + mt * 16 + r0 + half * 8;
                    g_om[(size_t)row * Ncat + col]     = acc[mt][nt][half * 2 + 0] + g_bcat[col];
                    g_om[(size_t)row * Ncat + col + 1] = acc[mt][nt][half * 2 + 1] + g_bcat[col + 1];
                }
            }
        }
    }
}

// ---- GEMM 3: out = BN(SiLU(g_ys @ w_out + b_out)) in NCHW -----------------
__global__ __launch_bounds__(256, 1)
void gemm_out(const float* __restrict__ Bw, const float* __restrict__ bias,
              const float* __restrict__ bn_g, const float* __restrict__ bn_b,
              const float* __restrict__ bn_m, const float* __restrict__ bn_v,
              float* __restrict__ out) {
    __shared__ unsigned short Ash[128][40];
    __shared__ unsigned short Asl[128][40];
    __shared__ unsigned short Bsh[32][136];
    __shared__ unsigned short Bsl[32][136];
    float acc[2][8][4];
    #pragma unroll
    for (int i = 0; i < 2; i++)
        #pragma unroll
        for (int j = 0; j < 8; j++)
            #pragma unroll
            for (int q = 0; q < 4; q++) acc[i][j][q] = 0.f;
    const int bm = blockIdx.y * 128;
    const int bnn = blockIdx.x * 128;
    gemm_core(g_ys, Bw, Cc, Cc, bm, bnn, Ash, Asl, Bsh, Bsl, acc);

    const int wid = threadIdx.x >> 5;
    const int lane = threadIdx.x & 31;
    const int wm = (wid >> 1) * 32;
    const int wn = (wid & 1) * 64;
    const int r0 = lane >> 2;
    const int c0 = (lane & 3) * 2;
    #pragma unroll
    for (int mt = 0; mt < 2; mt++) {
        #pragma unroll
        for (int nt = 0; nt < 8; nt++) {
            const int col = bnn + wn + nt * 8 + c0;
            const float s0 = bn_g[col] * rsqrtf(bn_v[col] + 1e-5f);
            const float s1 = bn_g[col + 1] * rsqrtf(bn_v[col + 1] + 1e-5f);
            #pragma unroll
            for (int half = 0; half < 2; half++) {
                const int row = bm + wm + mt * 16 + r0 + half * 8;
                const int bidx = row / HW;
                const int hw = row - bidx * HW;
                float y0 = acc[mt][nt][half * 2 + 0] + bias[col];
                float y1 = acc[mt][nt][half * 2 + 1] + bias[col + 1];
                y0 = (y0 - bn_m[col]) * s0 + bn_b[col];
                y1 = (y1 - bn_m[col + 1]) * s1 + bn_b[col + 1];
                out[((size_t)bidx * Cc + col) * HW + hw]       = y0 / (1.0f + expf(-y0));
                out[((size_t)bidx * Cc + col + 1) * HW + hw]   = y1 / (1.0f + expf(-y1));
            }
        }
    }
}

// ---------------- depthwise 3x3 + LayerNorm + exact GELU -------------------
__global__ __launch_bounds__(256)
void dw_ln_gelu(const float* __restrict__ wdw, const float* __restrict__ bdw,
                const float* __restrict__ lng, const float* __restrict__ lnb) {
    __shared__ float sred[256];
    const int m = blockIdx.x;
    const int b = m / HW;
    const int hw = m - b * HW;
    const int h = hw / Ww;
    const int w = hw - h * Ww;
    const int tid = threadIdx.x;
    const int c = tid * 2;

    float a0 = 0.f, a1 = 0.f;
    #pragma unroll
    for (int ky = 0; ky < 3; ky++) {
        const int hy = h + ky - 1;
        if ((unsigned)hy >= (unsigned)Hh) continue;
        #pragma unroll
        for (int kx = 0; kx < 3; kx++) {
            const int wx = w + kx - 1;
            if ((unsigned)wx >= (unsigned)Ww) continue;
            const float2 v = *(const float2*)&g_xh[((size_t)(b * HW + hy * Ww + wx)) * Cc + c];
            const float2 wv = *(const float2*)&wdw[(ky * 3 + kx) * Cc + c];
            a0 = fmaf(v.x, wv.x, a0);
            a1 = fmaf(v.y, wv.y, a1);
        }
    }
    const float2 bb2 = *(const float2*)&bdw[c];
    a0 += bb2.x; a1 += bb2.y;

    sred[tid] = a0 + a1;
    __syncthreads();
    for (int s = 128; s > 0; s >>= 1) {
        if (tid < s) sred[tid] += sred[tid + s];
        __syncthreads();
    }
    const float mu = sred[0] * (1.0f / 512.0f);
    __syncthreads();
    const float d0 = a0 - mu, d1 = a1 - mu;
    sred[tid] = d0 * d0 + d1 * d1;
    __syncthreads();
    for (int s = 128; s > 0; s >>= 1) {
        if (tid < s) sred[tid] += sred[tid + s];
        __syncthreads();
    }
    const float var = sred[0] * (1.0f / 512.0f);
    const float rstd = rsqrtf(var + 1e-6f);

    const float2 gg = *(const float2*)&lng[c];
    const float2 be = *(const float2*)&lnb[c];
    float o0 = d0 * rstd * gg.x + be.x;
    float o1 = d1 * rstd * gg.y + be.y;
    o0 = 0.5f * o0 * (1.0f + erff(o0 * 0.7071067811865475f));
    o1 = 0.5f * o1 * (1.0f + erff(o1 * 0.7071067811865475f));
    *(float2*)&g_x1[(size_t)m * Cc + c] = make_float2(o0, o1);
}

// ---------------- concat offset/mask weights -------------------------------
__global__ __launch_bounds__(256)
void concat_w(const float* __restrict__ w_off, const float* __restrict__ b_off,
              const float* __restrict__ w_mask, const float* __restrict__ b_mask) {
    const int idx = blockIdx.x * 256 + threadIdx.x;
    if (idx < Cc * Ncat) {
        const int k = idx / Ncat;
        const int n = idx - k * Ncat;
        g_wcat[idx] = (n < Noff) ? w_off[k * Noff + n] : w_mask[k * Nmsk + (n - Noff)];
    }
    if (idx < Ncat) g_bcat[idx] = (idx < Noff) ? b_off[idx] : b_mask[idx - Noff];
}

// ---------------- softmax over P for mask logits (in place) ----------------
__global__ __launch_bounds__(256)
void softmax_mask() {
    const int idx = blockIdx.x * 256 + threadIdx.x;
    if (idx >= Mtot * Gg) return;
    const int m = idx >> 4;
    const int g = idx & 15;
    float* p = g_om + (size_t)m * Ncat + Noff + g * Pp;
    float v[Pp];
    float mx = -1e30f;
    #pragma unroll
    for (int i = 0; i < Pp; i++) { v[i] = p[i]; mx = fmaxf(mx, v[i]); }
    float s = 0.f;
    #pragma unroll
    for (int i = 0; i < Pp; i++) { v[i] = expf(v[i] - mx); s += v[i]; }
    const float inv = 1.0f / s;
    #pragma unroll
    for (int i = 0; i < Pp; i++) p[i] = v[i] * inv;
}

// ---------------- DCNv3 bilinear sampling core -----------------------------
__device__ __forceinline__ float dcn_fetch(const float* __restrict__ base,
                                           int yu, int xu) {
    if ((unsigned)yu < (unsigned)Hh && (unsigned)xu < (unsigned)Ww)
        return base[(size_t)(yu * Ww + xu) * Cc];
    return 0.f;
}

__global__ __launch_bounds__(256)
void dcn_sample() {
    const int gid = blockIdx.x * 8 + (threadIdx.x >> 5);
    const int lane = threadIdx.x & 31;
    if (gid >= Mtot * Gg) return;
    const int m = gid >> 4;
    const int g = gid & 15;
    const int b = m / HW;
    const int hw = m - b * HW;
    const int h = hw / Ww;
    const int w = hw - h * Ww;

    const float rx = ((float)w + 1.5f) / 58.0f;
    const float ry = ((float)h + 1.5f) / 58.0f;

    const float* offp = g_om + (size_t)m * Ncat + g * (Pp * 2);
    const float* mskp = g_om + (size_t)m * Ncat + Noff + g * Pp;
    const float* base = g_xp + (size_t)b * HW * Cc + g * GC + lane;

    float acc = 0.f;
    #pragma unroll
    for (int p = 0; p < Pp; p++) {
        const int kx = p / 3;
        const int ky = p - kx * 3;
        const float ox = offp[2 * p];
        const float oy = offp[2 * p + 1];
        const float lx = (rx + (float)(kx - 1) / 58.0f) + ox / 58.0f;
        const float ly = (ry + (float)(ky - 1) / 58.0f) + oy / 58.0f;
        const float px = lx * 58.0f - 0.5f;
        const float py = ly * 58.0f - 0.5f;
        const float x0f = floorf(px);
        const float y0f = floorf(py);
        const float txf = px - x0f;
        const float tyf = py - y0f;
        const int x0 = (int)x0f;
        const int y0 = (int)y0f;
        const float msk = mskp[p];
        const float v00 = dcn_fetch(base, y0 - 1, x0 - 1);
        const float v01 = dcn_fetch(base, y0 - 1, x0);
        const float v10 = dcn_fetch(base, y0,     x0 - 1);
        const float v11 = dcn_fetch(base, y0,     x0);
        const float s = (1.f - tyf) * (1.f - txf) * v00
                      + (1.f - tyf) * txf * v01
                      + tyf * (1.f - txf) * v10
                      + tyf * txf * v11;
        acc = fmaf(msk, s, acc);
    }
    g_ys[(size_t)m * Cc + g * GC + lane] = acc;
}

// ---------------- host launch ----------------------------------------------
extern "C" void kernel_launch(void* const* d_in, const int* in_sizes, int n_in,
                              void* d_out, int out_size) {
    const float* x      = (const float*)d_in[0];
    const float* w_in   = (const float*)d_in[1];
    const float* b_in   = (const float*)d_in[2];
    const float* w_dw   = (const float*)d_in[3];
    const float* b_dw   = (const float*)d_in[4];
    const float* ln_g   = (const float*)d_in[5];
    const float* ln_b   = (const float*)d_in[6];
    const float* w_off  = (const float*)d_in[7];
    const float* b_off  = (const float*)d_in[8];
    const float* w_mask = (const float*)d_in[9];
    const float* b_mask = (const float*)d_in[10];
    const float* w_out  = (const float*)d_in[11];
    const float* b_out  = (const float*)d_in[12];
    const float* bn_g   = (const float*)d_in[13];
    const float* bn_b   = (const float*)d_in[14];
    const float* bn_m   = (const float*)d_in[15];
    const float* bn_v   = (const float*)d_in[16];

    // 1. NCHW -> NHWC
    nchw_to_nhwc<<<dim3(HW / 32, Cc / 32, Bn), dim3(32, 8)>>>(x);
    // 2. input_proj (tensor cores)
    gemm_in<<<dim3(Cc / 128, Mtot / 128), 256>>>(w_in, b_in);
    // 3. depthwise + LN + GELU
    dw_ln_gelu<<<Mtot, 256>>>(w_dw, b_dw, ln_g, ln_b);
    // 4. concat offset/mask weights
    concat_w<<<(Cc * Ncat + 255) / 256, 256>>>(w_off, b_off, w_mask, b_mask);
    // 5. offset/mask GEMM (tensor cores)
    gemm_om<<<dim3((Ncat + 127) / 128, Mtot / 128), 256>>>();
    // 6. softmax over P (in place on mask part)
    softmax_mask<<<(Mtot * Gg + 255) / 256, 256>>>();
    // 7. DCN sampling
    dcn_sample<<<(Mtot * Gg) / 8, 256>>>();
    // 8. output_proj + BN + SiLU, NCHW store (tensor cores)
    gemm_out<<<dim3(Cc / 128, Mtot / 128), 256>>>(w_out, b_out, bn_g, bn_b,
                                                  bn_m, bn_v, (float*)d_out);
}

// round 6
// speedup vs baseline: 1.8582x; 1.3333x over previous
#include <cuda_runtime.h>
#include <cuda_bf16.h>
#include <math.h>
#include <cstdint>

typedef unsigned int u32;
typedef unsigned short u16;

// Problem constants
#define Bn 4
#define Cc 512
#define Hh 56
#define Ww 56
#define Gg 16
#define Pp 9
#define GC 32
#define HW 3136          // 56*56
#define Mtot 12544       // B*H*W
#define Noff 288         // G*P*2
#define Nmsk 144         // G*P
#define Ncat 432         // Noff+Nmsk
#define NPAD 448         // Ncat padded to 64 multiple

// ---------------- scratch (device globals; no allocation allowed) ----------
__device__ float g_xh[Mtot * Cc];        // NHWC input fp32 (for depthwise)
__device__ u16   g_xh_h[Mtot * Cc];      // split halves for GEMM1 A
__device__ u16   g_xh_l[Mtot * Cc];
__device__ float g_xp[Mtot * Cc];        // input_proj output (for dcn)
__device__ u16   g_x1h[Mtot * Cc];       // dw+LN+GELU split (GEMM2 A)
__device__ u16   g_x1l[Mtot * Cc];
__device__ float g_om[Mtot * Ncat];      // [offset|mask]
__device__ u16   g_ysh[Mtot * Cc];       // DCN output split (GEMM3 A)
__device__ u16   g_ysl[Mtot * Cc];
__device__ u16   g_winh[Cc * Cc];        // w_in split
__device__ u16   g_winl[Cc * Cc];
__device__ u16   g_wcath[Cc * NPAD];     // padded concat weight split
__device__ u16   g_wcatl[Cc * NPAD];
__device__ u16   g_wouth[Cc * Cc];       // w_out split
__device__ u16   g_woutl[Cc * Cc];
__device__ float g_bcat[NPAD];

// ---------------- helpers ---------------------------------------------------
__device__ __forceinline__ void split2u(float v, u16& h, u16& l) {
    const __nv_bfloat16 hh = __float2bfloat16_rn(v);
    const float r = v - __bfloat162float(hh);
    h = __bfloat16_as_ushort(hh);
    l = __bfloat16_as_ushort(__float2bfloat16_rn(r));
}
__device__ __forceinline__ void ldmA4(u32* r, u32 addr) {
    asm volatile("ldmatrix.sync.aligned.m8n8.x4.shared.b16 {%0,%1,%2,%3}, [%4];\n"
                 : "=r"(r[0]), "=r"(r[1]), "=r"(r[2]), "=r"(r[3]) : "r"(addr));
}
__device__ __forceinline__ void ldmB2(u32* r, u32 addr) {
    asm volatile("ldmatrix.sync.aligned.m8n8.x2.trans.shared.b16 {%0,%1}, [%2];\n"
                 : "=r"(r[0]), "=r"(r[1]) : "r"(addr));
}
__device__ __forceinline__ void mma16816(float* c, const u32* a, const u32* b) {
    asm volatile("mma.sync.aligned.m16n8k16.row.col.f32.bf16.bf16.f32 "
                 "{%0,%1,%2,%3}, {%4,%5,%6,%7}, {%8,%9}, {%0,%1,%2,%3};\n"
                 : "+f"(c[0]), "+f"(c[1]), "+f"(c[2]), "+f"(c[3])
                 : "r"(a[0]), "r"(a[1]), "r"(a[2]), "r"(a[3]), "r"(b[0]), "r"(b[1]));
}
__device__ __forceinline__ void cpa16(u32 dst, const void* src) {
    asm volatile("cp.async.cg.shared.global [%0], [%1], 16;\n" :: "r"(dst), "l"(src));
}
__device__ __forceinline__ void cpcommit() { asm volatile("cp.async.commit_group;\n"); }
__device__ __forceinline__ void cpwait0() { asm volatile("cp.async.wait_group 0;\n"); }
__device__ __forceinline__ void cpwait1() { asm volatile("cp.async.wait_group 1;\n"); }

// ---------------- weight split setup ----------------------------------------
__global__ __launch_bounds__(256)
void split_w(const float* __restrict__ src, u16* __restrict__ dh,
             u16* __restrict__ dl, int n) {
    const int i = blockIdx.x * 256 + threadIdx.x;
    if (i < n) { u16 h, l; split2u(src[i], h, l); dh[i] = h; dl[i] = l; }
}

__global__ __launch_bounds__(256)
void build_wcat(const float* __restrict__ w_off, const float* __restrict__ b_off,
                const float* __restrict__ w_mask, const float* __restrict__ b_mask) {
    const int idx = blockIdx.x * 256 + threadIdx.x;
    if (idx < Cc * NPAD) {
        const int k = idx / NPAD;
        const int n = idx - k * NPAD;
        float v = 0.f;
        if (n < Noff) v = w_off[k * Noff + n];
        else if (n < Ncat) v = w_mask[k * Nmsk + (n - Noff)];
        u16 h, l; split2u(v, h, l);
        g_wcath[idx] = h; g_wcatl[idx] = l;
    }
    if (idx < NPAD)
        g_bcat[idx] = (idx < Noff) ? b_off[idx]
                     : (idx < Ncat ? b_mask[idx - Noff] : 0.f);
}

// ---------------- NCHW -> NHWC transpose (+ split) --------------------------
__global__ __launch_bounds__(256)
void nchw_to_nhwc(const float* __restrict__ x) {
    __shared__ float tile[32][33];
    const int bb = blockIdx.z;
    const int hw0 = blockIdx.x * 32;
    const int c0 = blockIdx.y * 32;
    const int tx = threadIdx.x;   // 32
    const int ty = threadIdx.y;   // 8
    const float* xb = x + (size_t)bb * Cc * HW;
    #pragma unroll
    for (int i = 0; i < 32; i += 8)
        tile[ty + i][tx] = xb[(size_t)(c0 + ty + i) * HW + hw0 + tx];
    __syncthreads();
    #pragma unroll
    for (int i = 0; i < 32; i += 8) {
        const size_t idx = ((size_t)bb * HW + hw0 + ty + i) * Cc + c0 + tx;
        const float v = tile[tx][ty + i];
        g_xh[idx] = v;
        u16 h, l; split2u(v, h, l);
        g_xh_h[idx] = h; g_xh_l[idx] = l;
    }
}

// ---------------- cp.async double-buffered split-bf16 GEMM core -------------
// Tiles: BM=128, BN=64, BK=32, 2 stages. Stage layout (ushort units):
//   A_hi [0,4096) A_lo [4096,8192) B_hi [8192,10240) B_lo [10240,12288)
// XOR swizzles: A chunk' = c ^ ((row>>1)&3); B chunk' = c ^ (k&7).
#define STG_U16 12288
#define STG_B   24576

__device__ __forceinline__ void pipe_issue(
    const u16* __restrict__ Ah, const u16* __restrict__ Al,
    const u16* __restrict__ Bh, const u16* __restrict__ Bl,
    int ldb, int K, int bm, int bn, int k0, u32 sb) {
    const int t = threadIdx.x;
    // A: thread -> row r = t>>1, chunks (t&1)*2, (t&1)*2+1 (16B each)
    const int r = t >> 1;
    const int c0 = (t & 1) * 2;
    const int rx = (r >> 1) & 3;
    const size_t asrc = (size_t)(bm + r) * K + k0;
    #pragma unroll
    for (int i = 0; i < 2; i++) {
        const int c = c0 + i;
        const u32 doff = (u32)(r * 32 + ((c ^ rx) << 3)) * 2;
        cpa16(sb + doff, (const void*)(Ah + asrc + c * 8));
        cpa16(sb + 8192 + doff, (const void*)(Al + asrc + c * 8));
    }
    // B: thread -> k row = t>>3, chunk = t&7
    const int k = t >> 3;
    const int cb = t & 7;
    const u32 bdoff = (u32)(k * 64 + ((cb ^ (k & 7)) << 3)) * 2;
    const size_t bsrc = (size_t)(k0 + k) * ldb + bn + cb * 8;
    cpa16(sb + 16384 + bdoff, (const void*)(Bh + bsrc));
    cpa16(sb + 20480 + bdoff, (const void*)(Bl + bsrc));
}

__device__ __forceinline__ void pipe_compute(u32 sb, int wm, int wn, int lane,
                                             float acc[2][4][4]) {
    const int row16 = lane & 15;
    const int chi = lane >> 4;          // 0/1
    #pragma unroll
    for (int ks = 0; ks < 32; ks += 16) {
        u32 aH[2][4], aL[2][4];
        #pragma unroll
        for (int mt = 0; mt < 2; mt++) {
            const int row = wm + mt * 16 + row16;
            const int ch = (ks >> 3) + chi;
            const u32 aoff = (u32)(row * 32 + ((ch ^ ((row >> 1) & 3)) << 3)) * 2;
            ldmA4(aH[mt], sb + aoff);
            ldmA4(aL[mt], sb + 8192 + aoff);
        }
        u32 bH[4][2], bL[4][2];
        #pragma unroll
        for (int nt = 0; nt < 4; nt++) {
            const int k = ks + row16;
            const int cn = (wn >> 3) + nt;
            const u32 boff = (u32)(k * 64 + ((cn ^ (k & 7)) << 3)) * 2;
            ldmB2(bH[nt], sb + 16384 + boff);
            ldmB2(bL[nt], sb + 20480 + boff);
        }
        #pragma unroll
        for (int mt = 0; mt < 2; mt++) {
            #pragma unroll
            for (int nt = 0; nt < 4; nt++) {
                mma16816(acc[mt][nt], aH[mt], bH[nt]);
                mma16816(acc[mt][nt], aH[mt], bL[nt]);
                mma16816(acc[mt][nt], aL[mt], bH[nt]);
            }
        }
    }
}

__device__ __forceinline__ void gemm_core2(
    const u16* __restrict__ Ah, const u16* __restrict__ Al,
    const u16* __restrict__ Bh, const u16* __restrict__ Bl,
    int ldb, int K, int bm, int bn, u32 smbase, float acc[2][4][4]) {
    const int wid = threadIdx.x >> 5;
    const int lane = threadIdx.x & 31;
    const int wm = (wid >> 1) * 32;
    const int wn = (wid & 1) * 32;
    const int nkt = K / 32;

    pipe_issue(Ah, Al, Bh, Bl, ldb, K, bm, bn, 0, smbase);
    cpcommit();
    for (int kt = 0; kt < nkt; kt++) {
        const u32 sb = smbase + (u32)(kt & 1) * STG_B;
        if (kt + 1 < nkt) {
            pipe_issue(Ah, Al, Bh, Bl, ldb, K, bm, bn, (kt + 1) * 32,
                       smbase + (u32)((kt + 1) & 1) * STG_B);
            cpcommit();
            cpwait1();
        } else {
            cpwait0();
        }
        __syncthreads();
        pipe_compute(sb, wm, wn, lane, acc);
        __syncthreads();
    }
}

// ---- GEMM 1: g_xp = xh @ w_in + b_in  (N=512) ------------------------------
__global__ __launch_bounds__(256, 2)
void gemm_in(const float* __restrict__ bias) {
    __shared__ u16 smem[2 * STG_U16];
    float acc[2][4][4];
    #pragma unroll
    for (int i = 0; i < 2; i++)
        #pragma unroll
        for (int j = 0; j < 4; j++)
            #pragma unroll
            for (int q = 0; q < 4; q++) acc[i][j][q] = 0.f;
    const int bm = blockIdx.y * 128;
    const int bnn = blockIdx.x * 64;
    const u32 smbase = (u32)__cvta_generic_to_shared(smem);
    gemm_core2(g_xh_h, g_xh_l, g_winh, g_winl, Cc, Cc, bm, bnn, smbase, acc);

    const int wid = threadIdx.x >> 5;
    const int lane = threadIdx.x & 31;
    const int wm = (wid >> 1) * 32;
    const int wn = (wid & 1) * 32;
    const int r0 = lane >> 2;
    const int c0 = (lane & 3) * 2;
    #pragma unroll
    for (int mt = 0; mt < 2; mt++) {
        #pragma unroll
        for (int nt = 0; nt < 4; nt++) {
            const int col = bnn + wn + nt * 8 + c0;
            #pragma unroll
            for (int half = 0; half < 2; half++) {
                const int row = bm + wm + mt * 16 + r0 + half * 8;
                g_xp[(size_t)row * Cc + col]     = acc[mt][nt][half * 2 + 0] + bias[col];
                g_xp[(size_t)row * Cc + col + 1] = acc[mt][nt][half * 2 + 1] + bias[col + 1];
            }
        }
    }
}

// ---- GEMM 2: g_om = x1 @ wcat + bcat  (N=448 padded, store 432) ------------
__global__ __launch_bounds__(256, 2)
void gemm_om() {
    __shared__ u16 smem[2 * STG_U16];
    float acc[2][4][4];
    #pragma unroll
    for (int i = 0; i < 2; i++)
        #pragma unroll
        for (int j = 0; j < 4; j++)
            #pragma unroll
            for (int q = 0; q < 4; q++) acc[i][j][q] = 0.f;
    const int bm = blockIdx.y * 128;
    const int bnn = blockIdx.x * 64;
    const u32 smbase = (u32)__cvta_generic_to_shared(smem);
    gemm_core2(g_x1h, g_x1l, g_wcath, g_wcatl, NPAD, Cc, bm, bnn, smbase, acc);

    const int wid = threadIdx.x >> 5;
    const int lane = threadIdx.x & 31;
    const int wm = (wid >> 1) * 32;
    const int wn = (wid & 1) * 32;
    const int r0 = lane >> 2;
    const int c0 = (lane & 3) * 2;
    #pragma unroll
    for (int mt = 0; mt < 2; mt++) {
        #pragma unroll
        for (int nt = 0; nt < 4; nt++) {
            const int col = bnn + wn + nt * 8 + c0;
            if (col < Ncat) {
                #pragma unroll
                for (int half = 0; half < 2; half++) {
                    const int row = bm + wm + mt * 16 + r0 + half * 8;
                    g_om[(size_t)row * Ncat + col]     = acc[mt][nt][half * 2 + 0] + g_bcat[col];
                    g_om[(size_t)row * Ncat + col + 1] = acc[mt][nt][half * 2 + 1] + g_bcat[col + 1];
                }
            }
        }
    }
}

// ---- GEMM 3: out = SiLU(BN(ys @ w_out + b_out)) in NCHW --------------------
__global__ __launch_bounds__(256, 2)
void gemm_out(const float* __restrict__ bias,
              const float* __restrict__ bn_g, const float* __restrict__ bn_b,
              const float* __restrict__ bn_m, const float* __restrict__ bn_v,
              float* __restrict__ out) {
    __shared__ u16 smem[2 * STG_U16];
    float acc[2][4][4];
    #pragma unroll
    for (int i = 0; i < 2; i++)
        #pragma unroll
        for (int j = 0; j < 4; j++)
            #pragma unroll
            for (int q = 0; q < 4; q++) acc[i][j][q] = 0.f;
    const int bm = blockIdx.y * 128;
    const int bnn = blockIdx.x * 64;
    const u32 smbase = (u32)__cvta_generic_to_shared(smem);
    gemm_core2(g_ysh, g_ysl, g_wouth, g_woutl, Cc, Cc, bm, bnn, smbase, acc);

    const int wid = threadIdx.x >> 5;
    const int lane = threadIdx.x & 31;
    const int wm = (wid >> 1) * 32;
    const int wn = (wid & 1) * 32;
    const int r0 = lane >> 2;
    const int c0 = (lane & 3) * 2;
    #pragma unroll
    for (int mt = 0; mt < 2; mt++) {
        #pragma unroll
        for (int nt = 0; nt < 4; nt++) {
            const int col = bnn + wn + nt * 8 + c0;
            const float s0 = bn_g[col] * rsqrtf(bn_v[col] + 1e-5f);
            const float s1 = bn_g[col + 1] * rsqrtf(bn_v[col + 1] + 1e-5f);
            #pragma unroll
            for (int half = 0; half < 2; half++) {
                const int row = bm + wm + mt * 16 + r0 + half * 8;
                const int bidx = row / HW;
                const int hw = row - bidx * HW;
                float y0 = acc[mt][nt][half * 2 + 0] + bias[col];
                float y1 = acc[mt][nt][half * 2 + 1] + bias[col + 1];
                y0 = (y0 - bn_m[col]) * s0 + bn_b[col];
                y1 = (y1 - bn_m[col + 1]) * s1 + bn_b[col + 1];
                out[((size_t)bidx * Cc + col) * HW + hw]     = y0 / (1.0f + expf(-y0));
                out[((size_t)bidx * Cc + col + 1) * HW + hw] = y1 / (1.0f + expf(-y1));
            }
        }
    }
}

// ---------------- depthwise 3x3 + LayerNorm + exact GELU (split out) -------
__global__ __launch_bounds__(256)
void dw_ln_gelu(const float* __restrict__ wdw, const float* __restrict__ bdw,
                const float* __restrict__ lng, const float* __restrict__ lnb) {
    __shared__ float sred[256];
    const int m = blockIdx.x;
    const int b = m / HW;
    const int hw = m - b * HW;
    const int h = hw / Ww;
    const int w = hw - h * Ww;
    const int tid = threadIdx.x;
    const int c = tid * 2;

    float a0 = 0.f, a1 = 0.f;
    #pragma unroll
    for (int ky = 0; ky < 3; ky++) {
        const int hy = h + ky - 1;
        if ((unsigned)hy >= (unsigned)Hh) continue;
        #pragma unroll
        for (int kx = 0; kx < 3; kx++) {
            const int wx = w + kx - 1;
            if ((unsigned)wx >= (unsigned)Ww) continue;
            const float2 v = *(const float2*)&g_xh[((size_t)(b * HW + hy * Ww + wx)) * Cc + c];
            const float2 wv = *(const float2*)&wdw[(ky * 3 + kx) * Cc + c];
            a0 = fmaf(v.x, wv.x, a0);
            a1 = fmaf(v.y, wv.y, a1);
        }
    }
    const float2 bb2 = *(const float2*)&bdw[c];
    a0 += bb2.x; a1 += bb2.y;

    sred[tid] = a0 + a1;
    __syncthreads();
    for (int s = 128; s > 0; s >>= 1) {
        if (tid < s) sred[tid] += sred[tid + s];
        __syncthreads();
    }
    const float mu = sred[0] * (1.0f / 512.0f);
    __syncthreads();
    const float d0 = a0 - mu, d1 = a1 - mu;
    sred[tid] = d0 * d0 + d1 * d1;
    __syncthreads();
    for (int s = 128; s > 0; s >>= 1) {
        if (tid < s) sred[tid] += sred[tid + s];
        __syncthreads();
    }
    const float var = sred[0] * (1.0f / 512.0f);
    const float rstd = rsqrtf(var + 1e-6f);

    const float2 gg = *(const float2*)&lng[c];
    const float2 be = *(const float2*)&lnb[c];
    float o0 = d0 * rstd * gg.x + be.x;
    float o1 = d1 * rstd * gg.y + be.y;
    o0 = 0.5f * o0 * (1.0f + erff(o0 * 0.7071067811865475f));
    o1 = 0.5f * o1 * (1.0f + erff(o1 * 0.7071067811865475f));
    u16 h0, l0, h1, l1;
    split2u(o0, h0, l0);
    split2u(o1, h1, l1);
    const size_t idx = (size_t)m * Cc + c;
    *(u32*)&g_x1h[idx] = (u32)h0 | ((u32)h1 << 16);
    *(u32*)&g_x1l[idx] = (u32)l0 | ((u32)l1 << 16);
}

// ---------------- softmax over P for mask logits (in place) ----------------
__global__ __launch_bounds__(256)
void softmax_mask() {
    const int idx = blockIdx.x * 256 + threadIdx.x;
    if (idx >= Mtot * Gg) return;
    const int m = idx >> 4;
    const int g = idx & 15;
    float* p = g_om + (size_t)m * Ncat + Noff + g * Pp;
    float v[Pp];
    float mx = -1e30f;
    #pragma unroll
    for (int i = 0; i < Pp; i++) { v[i] = p[i]; mx = fmaxf(mx, v[i]); }
    float s = 0.f;
    #pragma unroll
    for (int i = 0; i < Pp; i++) { v[i] = expf(v[i] - mx); s += v[i]; }
    const float inv = 1.0f / s;
    #pragma unroll
    for (int i = 0; i < Pp; i++) p[i] = v[i] * inv;
}

// ---------------- DCNv3 bilinear sampling core (split out) -----------------
__device__ __forceinline__ float dcn_fetch(const float* __restrict__ base,
                                           int yu, int xu) {
    if ((unsigned)yu < (unsigned)Hh && (unsigned)xu < (unsigned)Ww)
        return base[(size_t)(yu * Ww + xu) * Cc];
    return 0.f;
}

__global__ __launch_bounds__(256)
void dcn_sample() {
    const int gid = blockIdx.x * 8 + (threadIdx.x >> 5);
    const int lane = threadIdx.x & 31;
    if (gid >= Mtot * Gg) return;
    const int m = gid >> 4;
    const int g = gid & 15;
    const int b = m / HW;
    const int hw = m - b * HW;
    const int h = hw / Ww;
    const int w = hw - h * Ww;

    const float rx = ((float)w + 1.5f) / 58.0f;
    const float ry = ((float)h + 1.5f) / 58.0f;

    const float* offp = g_om + (size_t)m * Ncat + g * (Pp * 2);
    const float* mskp = g_om + (size_t)m * Ncat + Noff + g * Pp;
    const float* base = g_xp + (size_t)b * HW * Cc + g * GC + lane;

    float acc = 0.f;
    #pragma unroll
    for (int p = 0; p < Pp; p++) {
        const int kx = p / 3;
        const int ky = p - kx * 3;
        const float ox = offp[2 * p];
        const float oy = offp[2 * p + 1];
        const float lx = (rx + (float)(kx - 1) / 58.0f) + ox / 58.0f;
        const float ly = (ry + (float)(ky - 1) / 58.0f) + oy / 58.0f;
        const float px = lx * 58.0f - 0.5f;
        const float py = ly * 58.0f - 0.5f;
        const float x0f = floorf(px);
        const float y0f = floorf(py);
        const float txf = px - x0f;
        const float tyf = py - y0f;
        const int x0 = (int)x0f;
        const int y0 = (int)y0f;
        const float msk = mskp[p];
        const float v00 = dcn_fetch(base, y0 - 1, x0 - 1);
        const float v01 = dcn_fetch(base, y0 - 1, x0);
        const float v10 = dcn_fetch(base, y0,     x0 - 1);
        const float v11 = dcn_fetch(base, y0,     x0);
        const float s = (1.f - tyf) * (1.f - txf) * v00
                      + (1.f - tyf) * txf * v01
                      + tyf * (1.f - txf) * v10
                      + tyf * txf * v11;
        acc = fmaf(msk, s, acc);
    }
    const size_t oidx = (size_t)m * Cc + g * GC + lane;
    u16 hh, ll;
    split2u(acc, hh, ll);
    g_ysh[oidx] = hh;
    g_ysl[oidx] = ll;
}

// ---------------- host launch ----------------------------------------------
extern "C" void kernel_launch(void* const* d_in, const int* in_sizes, int n_in,
                              void* d_out, int out_size) {
    const float* x      = (const float*)d_in[0];
    const float* w_in   = (const float*)d_in[1];
    const float* b_in   = (const float*)d_in[2];
    const float* w_dw   = (const float*)d_in[3];
    const float* b_dw   = (const float*)d_in[4];
    const float* ln_g   = (const float*)d_in[5];
    const float* ln_b   = (const float*)d_in[6];
    const float* w_off  = (const float*)d_in[7];
    const float* b_off  = (const float*)d_in[8];
    const float* w_mask = (const float*)d_in[9];
    const float* b_mask = (const float*)d_in[10];
    const float* w_out  = (const float*)d_in[11];
    const float* b_out  = (const float*)d_in[12];
    const float* bn_g   = (const float*)d_in[13];
    const float* bn_b   = (const float*)d_in[14];
    const float* bn_m   = (const float*)d_in[15];
    const float* bn_v   = (const float*)d_in[16];

    u16 *winh, *winl, *wouth, *woutl;
    cudaGetSymbolAddress((void**)&winh, g_winh);
    cudaGetSymbolAddress((void**)&winl, g_winl);
    cudaGetSymbolAddress((void**)&wouth, g_wouth);
    cudaGetSymbolAddress((void**)&woutl, g_woutl);

    // 0. weight splits (+ padded concat)
    split_w<<<(Cc * Cc + 255) / 256, 256>>>(w_in, winh, winl, Cc * Cc);
    split_w<<<(Cc * Cc + 255) / 256, 256>>>(w_out, wouth, woutl, Cc * Cc);
    build_wcat<<<(Cc * NPAD + 255) / 256, 256>>>(w_off, b_off, w_mask, b_mask);
    // 1. NCHW -> NHWC (+ split)
    nchw_to_nhwc<<<dim3(HW / 32, Cc / 32, Bn), dim3(32, 8)>>>(x);
    // 2. input_proj (tensor cores, cp.async pipeline)
    gemm_in<<<dim3(Cc / 64, Mtot / 128), 256>>>(b_in);
    // 3. depthwise + LN + GELU (split out)
    dw_ln_gelu<<<Mtot, 256>>>(w_dw, b_dw, ln_g, ln_b);
    // 4. offset/mask GEMM
    gemm_om<<<dim3(NPAD / 64, Mtot / 128), 256>>>();
    // 5. softmax over P
    softmax_mask<<<(Mtot * Gg + 255) / 256, 256>>>();
    // 6. DCN sampling (split out)
    dcn_sample<<<(Mtot * Gg) / 8, 256>>>();
    // 7. output_proj + BN + SiLU, NCHW store
    gemm_out<<<dim3(Cc / 64, Mtot / 128), 256>>>(b_out, bn_g, bn_b, bn_m, bn_v,
                                                 (float*)d_out);
}

// round 7
// speedup vs baseline: 1.8663x; 1.0044x over previous
#include <cuda_runtime.h>
#include <cuda_bf16.h>
#include <math.h>
#include <cstdint>

typedef unsigned int u32;
typedef unsigned short u16;

// Problem constants
#define Bn 4
#define Cc 512
#define Hh 56
#define Ww 56
#define Gg 16
#define Pp 9
#define GC 32
#define HW 3136          // 56*56
#define Mtot 12544       // B*H*W
#define Noff 288         // G*P*2
#define Nmsk 144         // G*P
#define Ncat 432         // Noff+Nmsk
#define NPAD 448         // Ncat padded to 64 multiple

// ---------------- scratch (device globals; no allocation allowed) ----------
__device__ float g_xh[Mtot * Cc];        // NHWC input fp32 (for depthwise)
__device__ u16   g_xh_h[Mtot * Cc];      // split halves for GEMM1 A
__device__ u16   g_xh_l[Mtot * Cc];
__device__ float g_xp[Mtot * Cc];        // input_proj output (for dcn)
__device__ u16   g_x1h[Mtot * Cc];       // dw+LN+GELU split (GEMM2 A)
__device__ u16   g_x1l[Mtot * Cc];
__device__ float g_om[Mtot * Ncat];      // [offset|mask logits]
__device__ u16   g_ysh[Mtot * Cc];       // DCN output split (GEMM3 A)
__device__ u16   g_ysl[Mtot * Cc];
__device__ u16   g_winh[Cc * Cc];        // w_in split
__device__ u16   g_winl[Cc * Cc];
__device__ u16   g_wcath[Cc * NPAD];     // padded concat weight split
__device__ u16   g_wcatl[Cc * NPAD];
__device__ u16   g_wouth[Cc * Cc];       // w_out split
__device__ u16   g_woutl[Cc * Cc];
__device__ float g_bcat[NPAD];

// ---------------- helpers ---------------------------------------------------
__device__ __forceinline__ void split2u(float v, u16& h, u16& l) {
    const __nv_bfloat16 hh = __float2bfloat16_rn(v);
    const float r = v - __bfloat162float(hh);
    h = __bfloat16_as_ushort(hh);
    l = __bfloat16_as_ushort(__float2bfloat16_rn(r));
}
__device__ __forceinline__ void ldmA4(u32* r, u32 addr) {
    asm volatile("ldmatrix.sync.aligned.m8n8.x4.shared.b16 {%0,%1,%2,%3}, [%4];\n"
                 : "=r"(r[0]), "=r"(r[1]), "=r"(r[2]), "=r"(r[3]) : "r"(addr));
}
__device__ __forceinline__ void ldmB2(u32* r, u32 addr) {
    asm volatile("ldmatrix.sync.aligned.m8n8.x2.trans.shared.b16 {%0,%1}, [%2];\n"
                 : "=r"(r[0]), "=r"(r[1]) : "r"(addr));
}
__device__ __forceinline__ void mma16816(float* c, const u32* a, const u32* b) {
    asm volatile("mma.sync.aligned.m16n8k16.row.col.f32.bf16.bf16.f32 "
                 "{%0,%1,%2,%3}, {%4,%5,%6,%7}, {%8,%9}, {%0,%1,%2,%3};\n"
                 : "+f"(c[0]), "+f"(c[1]), "+f"(c[2]), "+f"(c[3])
                 : "r"(a[0]), "r"(a[1]), "r"(a[2]), "r"(a[3]), "r"(b[0]), "r"(b[1]));
}
__device__ __forceinline__ void cpa16(u32 dst, const void* src) {
    asm volatile("cp.async.cg.shared.global [%0], [%1], 16;\n" :: "r"(dst), "l"(src));
}
__device__ __forceinline__ void cpcommit() { asm volatile("cp.async.commit_group;\n"); }
__device__ __forceinline__ void cpwait_all() { asm volatile("cp.async.wait_group 0;\n"); }
__device__ __forceinline__ void cpwait_1() { asm volatile("cp.async.wait_group 1;\n"); }

// ---------------- weight split setup ----------------------------------------
__global__ __launch_bounds__(256)
void split_w(const float* __restrict__ src, u16* __restrict__ dh,
             u16* __restrict__ dl, int n) {
    const int i = blockIdx.x * 256 + threadIdx.x;
    if (i < n) { u16 h, l; split2u(src[i], h, l); dh[i] = h; dl[i] = l; }
}

__global__ __launch_bounds__(256)
void build_wcat(const float* __restrict__ w_off, const float* __restrict__ b_off,
                const float* __restrict__ w_mask, const float* __restrict__ b_mask) {
    const int idx = blockIdx.x * 256 + threadIdx.x;
    if (idx < Cc * NPAD) {
        const int k = idx / NPAD;
        const int n = idx - k * NPAD;
        float v = 0.f;
        if (n < Noff) v = w_off[k * Noff + n];
        else if (n < Ncat) v = w_mask[k * Nmsk + (n - Noff)];
        u16 h, l; split2u(v, h, l);
        g_wcath[idx] = h; g_wcatl[idx] = l;
    }
    if (idx < NPAD)
        g_bcat[idx] = (idx < Noff) ? b_off[idx]
                     : (idx < Ncat ? b_mask[idx - Noff] : 0.f);
}

// ---------------- NCHW -> NHWC transpose (+ split) --------------------------
__global__ __launch_bounds__(256)
void nchw_to_nhwc(const float* __restrict__ x) {
    __shared__ float tile[32][33];
    const int bb = blockIdx.z;
    const int hw0 = blockIdx.x * 32;
    const int c0 = blockIdx.y * 32;
    const int tx = threadIdx.x;   // 32
    const int ty = threadIdx.y;   // 8
    const float* xb = x + (size_t)bb * Cc * HW;
    #pragma unroll
    for (int i = 0; i < 32; i += 8)
        tile[ty + i][tx] = xb[(size_t)(c0 + ty + i) * HW + hw0 + tx];
    __syncthreads();
    #pragma unroll
    for (int i = 0; i < 32; i += 8) {
        const size_t idx = ((size_t)bb * HW + hw0 + ty + i) * Cc + c0 + tx;
        const float v = tile[tx][ty + i];
        g_xh[idx] = v;
        u16 h, l; split2u(v, h, l);
        g_xh_h[idx] = h; g_xh_l[idx] = l;
    }
}

// ---------------- 3-stage cp.async split-bf16 GEMM core ---------------------
// BM=128, BN=64, BK=32, 3 stages (dynamic smem 72KB). Stage layout (ushort):
//   A_hi [0,4096) A_lo [4096,8192) B_hi [8192,10240) B_lo [10240,12288)
// XOR swizzles: A chunk' = c ^ ((row>>1)&3); B chunk' = c ^ (k&7).
#define STG_U16 12288
#define STG_B   24576
#define DSMEM_B (3 * STG_B)

__device__ __forceinline__ void pipe_issue(
    const u16* __restrict__ Ah, const u16* __restrict__ Al,
    const u16* __restrict__ Bh, const u16* __restrict__ Bl,
    int ldb, int K, int bm, int bn, int k0, u32 sb) {
    const int t = threadIdx.x;
    const int r = t >> 1;
    const int c0 = (t & 1) * 2;
    const int rx = (r >> 1) & 3;
    const size_t asrc = (size_t)(bm + r) * K + k0;
    #pragma unroll
    for (int i = 0; i < 2; i++) {
        const int c = c0 + i;
        const u32 doff = (u32)(r * 32 + ((c ^ rx) << 3)) * 2;
        cpa16(sb + doff, (const void*)(Ah + asrc + c * 8));
        cpa16(sb + 8192 + doff, (const void*)(Al + asrc + c * 8));
    }
    const int k = t >> 3;
    const int cb = t & 7;
    const u32 bdoff = (u32)(k * 64 + ((cb ^ (k & 7)) << 3)) * 2;
    const size_t bsrc = (size_t)(k0 + k) * ldb + bn + cb * 8;
    cpa16(sb + 16384 + bdoff, (const void*)(Bh + bsrc));
    cpa16(sb + 20480 + bdoff, (const void*)(Bl + bsrc));
}

__device__ __forceinline__ void pipe_compute(u32 sb, int wm, int wn, int lane,
                                             float acc[2][4][4]) {
    const int row16 = lane & 15;
    const int chi = lane >> 4;          // 0/1
    #pragma unroll
    for (int ks = 0; ks < 32; ks += 16) {
        u32 aH[2][4], aL[2][4];
        #pragma unroll
        for (int mt = 0; mt < 2; mt++) {
            const int row = wm + mt * 16 + row16;
            const int ch = (ks >> 3) + chi;
            const u32 aoff = (u32)(row * 32 + ((ch ^ ((row >> 1) & 3)) << 3)) * 2;
            ldmA4(aH[mt], sb + aoff);
            ldmA4(aL[mt], sb + 8192 + aoff);
        }
        u32 bH[4][2], bL[4][2];
        #pragma unroll
        for (int nt = 0; nt < 4; nt++) {
            const int k = ks + row16;
            const int cn = (wn >> 3) + nt;
            const u32 boff = (u32)(k * 64 + ((cn ^ (k & 7)) << 3)) * 2;
            ldmB2(bH[nt], sb + 16384 + boff);
            ldmB2(bL[nt], sb + 20480 + boff);
        }
        #pragma unroll
        for (int mt = 0; mt < 2; mt++) {
            #pragma unroll
            for (int nt = 0; nt < 4; nt++) {
                mma16816(acc[mt][nt], aH[mt], bH[nt]);
                mma16816(acc[mt][nt], aH[mt], bL[nt]);
                mma16816(acc[mt][nt], aL[mt], bH[nt]);
            }
        }
    }
}

__device__ __forceinline__ void gemm_core3(
    const u16* __restrict__ Ah, const u16* __restrict__ Al,
    const u16* __restrict__ Bh, const u16* __restrict__ Bl,
    int ldb, int K, int bm, int bn, u32 smbase, float acc[2][4][4]) {
    const int wid = threadIdx.x >> 5;
    const int lane = threadIdx.x & 31;
    const int wm = (wid >> 1) * 32;
    const int wn = (wid & 1) * 32;
    const int nkt = K / 32;

    pipe_issue(Ah, Al, Bh, Bl, ldb, K, bm, bn, 0, smbase);
    cpcommit();
    pipe_issue(Ah, Al, Bh, Bl, ldb, K, bm, bn, 32, smbase + STG_B);
    cpcommit();
    int stg = 0;
    for (int kt = 0; kt < nkt; kt++) {
        if (kt == nkt - 1) cpwait_all(); else cpwait_1();
        __syncthreads();
        if (kt + 2 < nkt) {
            int s2 = stg + 2; if (s2 >= 3) s2 -= 3;
            pipe_issue(Ah, Al, Bh, Bl, ldb, K, bm, bn, (kt + 2) * 32,
                       smbase + (u32)s2 * STG_B);
            cpcommit();
        }
        pipe_compute(smbase + (u32)stg * STG_B, wm, wn, lane, acc);
        if (++stg == 3) stg = 0;
    }
}

// ---- GEMM 1: g_xp = xh @ w_in + b_in  (N=512) ------------------------------
__global__ __launch_bounds__(256, 2)
void gemm_in(const float* __restrict__ bias) {
    extern __shared__ u16 smem[];
    float acc[2][4][4];
    #pragma unroll
    for (int i = 0; i < 2; i++)
        #pragma unroll
        for (int j = 0; j < 4; j++)
            #pragma unroll
            for (int q = 0; q < 4; q++) acc[i][j][q] = 0.f;
    const int bm = blockIdx.y * 128;
    const int bnn = blockIdx.x * 64;
    const u32 smbase = (u32)__cvta_generic_to_shared(smem);
    gemm_core3(g_xh_h, g_xh_l, g_winh, g_winl, Cc, Cc, bm, bnn, smbase, acc);

    const int wid = threadIdx.x >> 5;
    const int lane = threadIdx.x & 31;
    const int wm = (wid >> 1) * 32;
    const int wn = (wid & 1) * 32;
    const int r0 = lane >> 2;
    const int c0 = (lane & 3) * 2;
    #pragma unroll
    for (int mt = 0; mt < 2; mt++) {
        #pragma unroll
        for (int nt = 0; nt < 4; nt++) {
            const int col = bnn + wn + nt * 8 + c0;
            #pragma unroll
            for (int half = 0; half < 2; half++) {
                const int row = bm + wm + mt * 16 + r0 + half * 8;
                g_xp[(size_t)row * Cc + col]     = acc[mt][nt][half * 2 + 0] + bias[col];
                g_xp[(size_t)row * Cc + col + 1] = acc[mt][nt][half * 2 + 1] + bias[col + 1];
            }
        }
    }
}

// ---- GEMM 2: g_om = x1 @ wcat + bcat  (N=448 padded, store 432) ------------
__global__ __launch_bounds__(256, 2)
void gemm_om() {
    extern __shared__ u16 smem[];
    float acc[2][4][4];
    #pragma unroll
    for (int i = 0; i < 2; i++)
        #pragma unroll
        for (int j = 0; j < 4; j++)
            #pragma unroll
            for (int q = 0; q < 4; q++) acc[i][j][q] = 0.f;
    const int bm = blockIdx.y * 128;
    const int bnn = blockIdx.x * 64;
    const u32 smbase = (u32)__cvta_generic_to_shared(smem);
    gemm_core3(g_x1h, g_x1l, g_wcath, g_wcatl, NPAD, Cc, bm, bnn, smbase, acc);

    const int wid = threadIdx.x >> 5;
    const int lane = threadIdx.x & 31;
    const int wm = (wid >> 1) * 32;
    const int wn = (wid & 1) * 32;
    const int r0 = lane >> 2;
    const int c0 = (lane & 3) * 2;
    #pragma unroll
    for (int mt = 0; mt < 2; mt++) {
        #pragma unroll
        for (int nt = 0; nt < 4; nt++) {
            const int col = bnn + wn + nt * 8 + c0;
            if (col < Ncat) {
                #pragma unroll
                for (int half = 0; half < 2; half++) {
                    const int row = bm + wm + mt * 16 + r0 + half * 8;
                    g_om[(size_t)row * Ncat + col]     = acc[mt][nt][half * 2 + 0] + g_bcat[col];
                    g_om[(size_t)row * Ncat + col + 1] = acc[mt][nt][half * 2 + 1] + g_bcat[col + 1];
                }
            }
        }
    }
}

// ---- GEMM 3: out = SiLU(BN(ys @ w_out + b_out)) in NCHW --------------------
__global__ __launch_bounds__(256, 2)
void gemm_out(const float* __restrict__ bias,
              const float* __restrict__ bn_g, const float* __restrict__ bn_b,
              const float* __restrict__ bn_m, const float* __restrict__ bn_v,
              float* __restrict__ out) {
    extern __shared__ u16 smem[];
    float acc[2][4][4];
    #pragma unroll
    for (int i = 0; i < 2; i++)
        #pragma unroll
        for (int j = 0; j < 4; j++)
            #pragma unroll
            for (int q = 0; q < 4; q++) acc[i][j][q] = 0.f;
    const int bm = blockIdx.y * 128;
    const int bnn = blockIdx.x * 64;
    const u32 smbase = (u32)__cvta_generic_to_shared(smem);
    gemm_core3(g_ysh, g_ysl, g_wouth, g_woutl, Cc, Cc, bm, bnn, smbase, acc);

    const int wid = threadIdx.x >> 5;
    const int lane = threadIdx.x & 31;
    const int wm = (wid >> 1) * 32;
    const int wn = (wid & 1) * 32;
    const int r0 = lane >> 2;
    const int c0 = (lane & 3) * 2;
    #pragma unroll
    for (int mt = 0; mt < 2; mt++) {
        #pragma unroll
        for (int nt = 0; nt < 4; nt++) {
            const int col = bnn + wn + nt * 8 + c0;
            const float s0 = bn_g[col] * rsqrtf(bn_v[col] + 1e-5f);
            const float s1 = bn_g[col + 1] * rsqrtf(bn_v[col + 1] + 1e-5f);
            #pragma unroll
            for (int half = 0; half < 2; half++) {
                const int row = bm + wm + mt * 16 + r0 + half * 8;
                const int bidx = row / HW;
                const int hw = row - bidx * HW;
                float y0 = acc[mt][nt][half * 2 + 0] + bias[col];
                float y1 = acc[mt][nt][half * 2 + 1] + bias[col + 1];
                y0 = (y0 - bn_m[col]) * s0 + bn_b[col];
                y1 = (y1 - bn_m[col + 1]) * s1 + bn_b[col + 1];
                out[((size_t)bidx * Cc + col) * HW + hw]     = y0 / (1.0f + expf(-y0));
                out[((size_t)bidx * Cc + col + 1) * HW + hw] = y1 / (1.0f + expf(-y1));
            }
        }
    }
}

// ---------------- depthwise 3x3 + LayerNorm + exact GELU (split out) -------
__global__ __launch_bounds__(256)
void dw_ln_gelu(const float* __restrict__ wdw, const float* __restrict__ bdw,
                const float* __restrict__ lng, const float* __restrict__ lnb) {
    __shared__ float sredA[8];
    __shared__ float sredB[8];
    const int m = blockIdx.x;
    const int b = m / HW;
    const int hw = m - b * HW;
    const int h = hw / Ww;
    const int w = hw - h * Ww;
    const int tid = threadIdx.x;
    const int wid = tid >> 5;
    const int lane = tid & 31;
    const int c = tid * 2;

    float a0 = 0.f, a1 = 0.f;
    #pragma unroll
    for (int ky = 0; ky < 3; ky++) {
        const int hy = h + ky - 1;
        if ((unsigned)hy >= (unsigned)Hh) continue;
        #pragma unroll
        for (int kx = 0; kx < 3; kx++) {
            const int wx = w + kx - 1;
            if ((unsigned)wx >= (unsigned)Ww) continue;
            const float2 v = *(const float2*)&g_xh[((size_t)(b * HW + hy * Ww + wx)) * Cc + c];
            const float2 wv = *(const float2*)&wdw[(ky * 3 + kx) * Cc + c];
            a0 = fmaf(v.x, wv.x, a0);
            a1 = fmaf(v.y, wv.y, a1);
        }
    }
    const float2 bb2 = *(const float2*)&bdw[c];
    a0 += bb2.x; a1 += bb2.y;

    // mean via warp shuffles + one cross-warp stage
    float part = a0 + a1;
    #pragma unroll
    for (int s = 16; s > 0; s >>= 1) part += __shfl_xor_sync(0xffffffffu, part, s);
    if (lane == 0) sredA[wid] = part;
    __syncthreads();
    float mu = 0.f;
    #pragma unroll
    for (int i = 0; i < 8; i++) mu += sredA[i];
    mu *= (1.0f / 512.0f);

    const float d0 = a0 - mu, d1 = a1 - mu;
    float vpart = d0 * d0 + d1 * d1;
    #pragma unroll
    for (int s = 16; s > 0; s >>= 1) vpart += __shfl_xor_sync(0xffffffffu, vpart, s);
    if (lane == 0) sredB[wid] = vpart;
    __syncthreads();
    float var = 0.f;
    #pragma unroll
    for (int i = 0; i < 8; i++) var += sredB[i];
    var *= (1.0f / 512.0f);
    const float rstd = rsqrtf(var + 1e-6f);

    const float2 gg = *(const float2*)&lng[c];
    const float2 be = *(const float2*)&lnb[c];
    float o0 = d0 * rstd * gg.x + be.x;
    float o1 = d1 * rstd * gg.y + be.y;
    o0 = 0.5f * o0 * (1.0f + erff(o0 * 0.7071067811865475f));
    o1 = 0.5f * o1 * (1.0f + erff(o1 * 0.7071067811865475f));
    u16 h0, l0, h1, l1;
    split2u(o0, h0, l0);
    split2u(o1, h1, l1);
    const size_t idx = (size_t)m * Cc + c;
    *(u32*)&g_x1h[idx] = (u32)h0 | ((u32)h1 << 16);
    *(u32*)&g_x1l[idx] = (u32)l0 | ((u32)l1 << 16);
}

// ---------------- DCNv3 sampling + fused softmax ---------------------------
__device__ __forceinline__ float dcn_fetch(const float* __restrict__ base,
                                           int yu, int xu) {
    if ((unsigned)yu < (unsigned)Hh && (unsigned)xu < (unsigned)Ww)
        return base[(size_t)(yu * Ww + xu) * Cc];
    return 0.f;
}

__global__ __launch_bounds__(256)
void dcn_sample() {
    const int gid = blockIdx.x * 8 + (threadIdx.x >> 5);
    const int lane = threadIdx.x & 31;
    if (gid >= Mtot * Gg) return;
    const int m = gid >> 4;
    const int g = gid & 15;
    const int b = m / HW;
    const int hw = m - b * HW;
    const int h = hw / Ww;
    const int w = hw - h * Ww;

    const float rx = ((float)w + 1.5f) / 58.0f;
    const float ry = ((float)h + 1.5f) / 58.0f;

    const float* offp = g_om + (size_t)m * Ncat + g * (Pp * 2);
    const float* mskp = g_om + (size_t)m * Ncat + Noff + g * Pp;
    const float* base = g_xp + (size_t)b * HW * Cc + g * GC + lane;

    // fused softmax over the 9 mask logits (redundant per lane; broadcast loads)
    float logit[Pp];
    float mx = -1e30f;
    #pragma unroll
    for (int p = 0; p < Pp; p++) { logit[p] = mskp[p]; mx = fmaxf(mx, logit[p]); }
    float ssum = 0.f;
    #pragma unroll
    for (int p = 0; p < Pp; p++) { logit[p] = expf(logit[p] - mx); ssum += logit[p]; }
    const float sinv = 1.0f / ssum;

    float acc = 0.f;
    #pragma unroll
    for (int p = 0; p < Pp; p++) {
        const int kx = p / 3;
        const int ky = p - kx * 3;
        const float ox = offp[2 * p];
        const float oy = offp[2 * p + 1];
        const float lx = (rx + (float)(kx - 1) / 58.0f) + ox / 58.0f;
        const float ly = (ry + (float)(ky - 1) / 58.0f) + oy / 58.0f;
        const float px = lx * 58.0f - 0.5f;
        const float py = ly * 58.0f - 0.5f;
        const float x0f = floorf(px);
        const float y0f = floorf(py);
        const float txf = px - x0f;
        const float tyf = py - y0f;
        const int x0 = (int)x0f;
        const int y0 = (int)y0f;
        const float msk = logit[p] * sinv;
        const float v00 = dcn_fetch(base, y0 - 1, x0 - 1);
        const float v01 = dcn_fetch(base, y0 - 1, x0);
        const float v10 = dcn_fetch(base, y0,     x0 - 1);
        const float v11 = dcn_fetch(base, y0,     x0);
        const float s = (1.f - tyf) * (1.f - txf) * v00
                      + (1.f - tyf) * txf * v01
                      + tyf * (1.f - txf) * v10
                      + tyf * txf * v11;
        acc = fmaf(msk, s, acc);
    }
    const size_t oidx = (size_t)m * Cc + g * GC + lane;
    u16 hh, ll;
    split2u(acc, hh, ll);
    g_ysh[oidx] = hh;
    g_ysl[oidx] = ll;
}

// ---------------- host launch ----------------------------------------------
extern "C" void kernel_launch(void* const* d_in, const int* in_sizes, int n_in,
                              void* d_out, int out_size) {
    const float* x      = (const float*)d_in[0];
    const float* w_in   = (const float*)d_in[1];
    const float* b_in   = (const float*)d_in[2];
    const float* w_dw   = (const float*)d_in[3];
    const float* b_dw   = (const float*)d_in[4];
    const float* ln_g   = (const float*)d_in[5];
    const float* ln_b   = (const float*)d_in[6];
    const float* w_off  = (const float*)d_in[7];
    const float* b_off  = (const float*)d_in[8];
    const float* w_mask = (const float*)d_in[9];
    const float* b_mask = (const float*)d_in[10];
    const float* w_out  = (const float*)d_in[11];
    const float* b_out  = (const float*)d_in[12];
    const float* bn_g   = (const float*)d_in[13];
    const float* bn_b   = (const float*)d_in[14];
    const float* bn_m   = (const float*)d_in[15];
    const float* bn_v   = (const float*)d_in[16];

    u16 *winh, *winl, *wouth, *woutl;
    cudaGetSymbolAddress((void**)&winh, g_winh);
    cudaGetSymbolAddress((void**)&winl, g_winl);
    cudaGetSymbolAddress((void**)&wouth, g_wouth);
    cudaGetSymbolAddress((void**)&woutl, g_woutl);

    static int smem_set = 0;
    if (!smem_set) {
        cudaFuncSetAttribute(gemm_in, cudaFuncAttributeMaxDynamicSharedMemorySize, DSMEM_B);
        cudaFuncSetAttribute(gemm_om, cudaFuncAttributeMaxDynamicSharedMemorySize, DSMEM_B);
        cudaFuncSetAttribute(gemm_out, cudaFuncAttributeMaxDynamicSharedMemorySize, DSMEM_B);
        smem_set = 1;
    }

    // 0. weight splits (+ padded concat)
    split_w<<<(Cc * Cc + 255) / 256, 256>>>(w_in, winh, winl, Cc * Cc);
    split_w<<<(Cc * Cc + 255) / 256, 256>>>(w_out, wouth, woutl, Cc * Cc);
    build_wcat<<<(Cc * NPAD + 255) / 256, 256>>>(w_off, b_off, w_mask, b_mask);
    // 1. NCHW -> NHWC (+ split)
    nchw_to_nhwc<<<dim3(HW / 32, Cc / 32, Bn), dim3(32, 8)>>>(x);
    // 2. input_proj
    gemm_in<<<dim3(Cc / 64, Mtot / 128), 256, DSMEM_B>>>(b_in);
    // 3. depthwise + LN + GELU
    dw_ln_gelu<<<Mtot, 256>>>(w_dw, b_dw, ln_g, ln_b);
    // 4. offset/mask GEMM (raw logits; softmax fused into dcn_sample)
    gemm_om<<<dim3(NPAD / 64, Mtot / 128), 256, DSMEM_B>>>();
    // 5. DCN sampling (+softmax, split out)
    dcn_sample<<<(Mtot * Gg) / 8, 256>>>();
    // 6. output_proj + BN + SiLU, NCHW store
    gemm_out<<<dim3(Cc / 64, Mtot / 128), 256, DSMEM_B>>>(b_out, bn_g, bn_b,
                                                          bn_m, bn_v, (float*)d_out);
}

// round 10
// speedup vs baseline: 1.9435x; 1.0414x over previous
#include <cuda_runtime.h>
#include <cuda_bf16.h>
#include <math.h>
#include <cstdint>

typedef unsigned int u32;
typedef unsigned short u16;
typedef unsigned long long u64;

// Problem constants
#define Bn 4
#define Cc 512
#define Hh 56
#define Ww 56
#define Gg 16
#define Pp 9
#define GC 32
#define HW 3136          // 56*56
#define Mtot 12544       // B*H*W
#define Noff 288         // G*P*2
#define Nmsk 144         // G*P
#define Ncat 432         // Noff+Nmsk
#define NPAD 512         // Ncat padded to 128 multiple

// ---------------- scratch (device globals; no allocation allowed) ----------
__device__ float g_xh[Mtot * Cc];        // NHWC input fp32 (for depthwise)
__device__ float g_xa[Mtot * Cc];        // tf32-rounded NHWC (GEMM1 A)
__device__ float g_xp[Mtot * Cc];        // input_proj output (for dcn)
__device__ float g_x1[Mtot * Cc];        // dw+LN+GELU, tf32-rounded (GEMM2 A)
__device__ float g_om[Mtot * Ncat];      // [offset|mask logits]
__device__ u16   g_ysh[Mtot * Cc];       // DCN output split (GEMM3 A)
__device__ u16   g_ysl[Mtot * Cc];
__device__ float g_winT[Cc * Cc];        // w_in^T tf32-rounded: [n][k]
__device__ float g_wcatT[NPAD * Cc];     // concat weight^T tf32-rounded: [n][k]
__device__ u16   g_wouth[Cc * Cc];       // w_out split (bf16 hi): [k][n]
__device__ u16   g_woutl[Cc * Cc];       // [k][n]
__device__ float g_bcat[NPAD];

// ---------------- helpers ---------------------------------------------------
__device__ __forceinline__ void split2u(float v, u16& h, u16& l) {
    const __nv_bfloat16 hh = __float2bfloat16_rn(v);
    const float r = v - __bfloat162float(hh);
    h = __bfloat16_as_ushort(hh);
    l = __bfloat16_as_ushort(__float2bfloat16_rn(r));
}
__device__ __forceinline__ float tf32r(float v) {
    u32 r;
    asm("cvt.rna.tf32.f32 %0, %1;" : "=r"(r) : "f"(v));
    return __uint_as_float(r);
}
__device__ __forceinline__ void ldmA4(u32* r, u32 addr) {
    asm volatile("ldmatrix.sync.aligned.m8n8.x4.shared.b16 {%0,%1,%2,%3}, [%4];\n"
                 : "=r"(r[0]), "=r"(r[1]), "=r"(r[2]), "=r"(r[3]) : "r"(addr));
}
__device__ __forceinline__ void ldmB2t(u32* r, u32 addr) {
    asm volatile("ldmatrix.sync.aligned.m8n8.x2.trans.shared.b16 {%0,%1}, [%2];\n"
                 : "=r"(r[0]), "=r"(r[1]) : "r"(addr));
}
__device__ __forceinline__ void ldmB2(u32* r, u32 addr) {
    asm volatile("ldmatrix.sync.aligned.m8n8.x2.shared.b16 {%0,%1}, [%2];\n"
                 : "=r"(r[0]), "=r"(r[1]) : "r"(addr));
}
__device__ __forceinline__ void mma16816(float* c, const u32* a, const u32* b) {
    asm volatile("mma.sync.aligned.m16n8k16.row.col.f32.bf16.bf16.f32 "
                 "{%0,%1,%2,%3}, {%4,%5,%6,%7}, {%8,%9}, {%0,%1,%2,%3};\n"
                 : "+f"(c[0]), "+f"(c[1]), "+f"(c[2]), "+f"(c[3])
                 : "r"(a[0]), "r"(a[1]), "r"(a[2]), "r"(a[3]), "r"(b[0]), "r"(b[1]));
}
__device__ __forceinline__ void mma_tf32(float* c, const u32* a, const u32* b) {
    asm volatile("mma.sync.aligned.m16n8k8.row.col.f32.tf32.tf32.f32 "
                 "{%0,%1,%2,%3}, {%4,%5,%6,%7}, {%8,%9}, {%0,%1,%2,%3};\n"
                 : "+f"(c[0]), "+f"(c[1]), "+f"(c[2]), "+f"(c[3])
                 : "r"(a[0]), "r"(a[1]), "r"(a[2]), "r"(a[3]), "r"(b[0]), "r"(b[1]));
}
__device__ __forceinline__ void cpa16(u32 dst, const void* src) {
    asm volatile("cp.async.cg.shared.global [%0], [%1], 16;\n" :: "r"(dst), "l"(src));
}
__device__ __forceinline__ void cpcommit() { asm volatile("cp.async.commit_group;\n"); }
__device__ __forceinline__ void cpwait0() { asm volatile("cp.async.wait_group 0;\n"); }
__device__ __forceinline__ void cpwait1() { asm volatile("cp.async.wait_group 1;\n"); }

// ---------------- weight setup ----------------------------------------------
// w_out: split bf16 [k][n] (for bf16x3 GEMM3)
__global__ __launch_bounds__(256)
void split_w(const float* __restrict__ src, u16* __restrict__ dh,
             u16* __restrict__ dl, int n) {
    const int i = blockIdx.x * 256 + threadIdx.x;
    if (i < n) { u16 h, l; split2u(src[i], h, l); dh[i] = h; dl[i] = l; }
}
// w_in: transpose to [n][k], tf32-rounded fp32
__global__ __launch_bounds__(256)
void split_w32T(const float* __restrict__ src, float* __restrict__ dst) {
    const int i = blockIdx.x * 256 + threadIdx.x;
    if (i < Cc * Cc) {
        const int k = i >> 9;
        const int n = i & 511;
        dst[n * Cc + k] = tf32r(src[i]);
    }
}
// concat offset/mask weights: [n][k] tf32-rounded, n padded to 512
__global__ __launch_bounds__(256)
void build_wcat32(const float* __restrict__ w_off, const float* __restrict__ b_off,
                  const float* __restrict__ w_mask, const float* __restrict__ b_mask) {
    const int i = blockIdx.x * 256 + threadIdx.x;
    if (i < NPAD * Cc) {
        const int n = i >> 9;
        const int k = i & 511;
        float v = 0.f;
        if (n < Noff) v = w_off[k * Noff + n];
        else if (n < Ncat) v = w_mask[k * Nmsk + (n - Noff)];
        g_wcatT[i] = tf32r(v);
    }
    if (i < NPAD)
        g_bcat[i] = (i < Noff) ? b_off[i] : (i < Ncat ? b_mask[i - Noff] : 0.f);
}

// ---------------- NCHW -> NHWC transpose (+ tf32 copy) ----------------------
__global__ __launch_bounds__(256)
void nchw_to_nhwc(const float* __restrict__ x) {
    __shared__ float tile[32][33];
    const int bb = blockIdx.z;
    const int hw0 = blockIdx.x * 32;
    const int c0 = blockIdx.y * 32;
    const int tx = threadIdx.x;
    const int ty = threadIdx.y;
    const float* xb = x + (size_t)bb * Cc * HW;
    #pragma unroll
    for (int i = 0; i < 32; i += 8)
        tile[ty + i][tx] = xb[(size_t)(c0 + ty + i) * HW + hw0 + tx];
    __syncthreads();
    #pragma unroll
    for (int i = 0; i < 32; i += 8) {
        const size_t idx = ((size_t)bb * HW + hw0 + ty + i) * Cc + c0 + tx;
        const float v = tile[tx][ty + i];
        g_xh[idx] = v;
        g_xa[idx] = tf32r(v);
    }
}

// ================= tf32 GEMM: BM=128 BN=128 BK=32, 3-stage ==================
// Stage (32768 B): A [0,16K) rows 128x128B; B [16K,32K) rows 128x128B ([n][k])
// XOR swizzle: 16B chunk c at row r -> c ^ (r&7).
#define TF_STG 32768
#define TF_DSMEM (3 * TF_STG)

__device__ __forceinline__ void tf_fill(const float* __restrict__ A,
                                        const float* __restrict__ B,
                                        int bm, int bn, int kt, u32 stg) {
    const int t = threadIdx.x;
    const int row = t >> 1;
    const int cb = (t & 1) * 4;
    const size_t ka = (size_t)(bm + row) * Cc + kt * 32;
    const size_t kb = (size_t)(bn + row) * Cc + kt * 32;
    #pragma unroll
    for (int i = 0; i < 4; i++) {
        const int c = cb + i;
        const u32 d = (u32)(row * 128 + ((c ^ (row & 7)) << 4));
        cpa16(stg + d,         (const void*)(A + ka + c * 4));
        cpa16(stg + 16384 + d, (const void*)(B + kb + c * 4));
    }
    cpcommit();
}

__device__ __forceinline__ void tf_compute(u32 stg, int wm, int wn, int lane,
                                           float acc[4][4][4]) {
    const u32 stgB = stg + 16384;
    const int arow7 = lane & 7;
    const int arow8 = ((lane >> 3) & 1) * 8;
    const int achk = lane >> 4;             // 0/1
    #pragma unroll
    for (int ks = 0; ks < 4; ks++) {
        u32 a[4][4];
        #pragma unroll
        for (int mf = 0; mf < 4; mf++) {
            const int row = wm + mf * 16 + arow7 + arow8;
            const int ch = 2 * ks + achk;
            ldmA4(a[mf], stg + (u32)(row * 128 + ((ch ^ (row & 7)) << 4)));
        }
        u32 b[4][2];
        #pragma unroll
        for (int nf = 0; nf < 4; nf++) {
            const int row = wn + nf * 8 + arow7;       // lanes 0..15 used
            const int ch = 2 * ks + ((lane >> 3) & 1);
            ldmB2(b[nf], stgB + (u32)(row * 128 + ((ch ^ (row & 7)) << 4)));
        }
        #pragma unroll
        for (int mf = 0; mf < 4; mf++)
            #pragma unroll
            for (int nf = 0; nf < 4; nf++)
                mma_tf32(acc[mf][nf], a[mf], b[nf]);
    }
}

__device__ __forceinline__ void tf_core(const float* __restrict__ A,
                                        const float* __restrict__ B,
                                        int bm, int bn, u32 smbase,
                                        float acc[4][4][4]) {
    const int wid = threadIdx.x >> 5;
    const int lane = threadIdx.x & 31;
    const int wm = (wid & 1) * 64;
    const int wn = (wid >> 1) * 32;
    const u32 st[3] = {smbase, smbase + TF_STG, smbase + 2 * TF_STG};
    tf_fill(A, B, bm, bn, 0, st[0]);
    tf_fill(A, B, bm, bn, 1, st[1]);
    #pragma unroll 1
    for (int kt = 0; kt < 16; kt++) {
        if (kt == 15) cpwait0(); else cpwait1();
        __syncthreads();
        if (kt + 2 < 16) {
            int s2 = kt + 2; s2 -= (s2 / 3) * 3;
            tf_fill(A, B, bm, bn, kt + 2, st[s2]);
        }
        int s = kt; s -= (s / 3) * 3;
        tf_compute(st[s], wm, wn, lane, acc);
    }
}

// ---- GEMM 1 (tf32): g_xp = xa @ winT^T + b_in ------------------------------
__global__ __launch_bounds__(256, 2)
void gemm_in(const float* __restrict__ bias) {
    extern __shared__ char smem[];
    const u32 smbase = (u32)__cvta_generic_to_shared(smem);
    float acc[4][4][4];
    #pragma unroll
    for (int i = 0; i < 4; i++)
        #pragma unroll
        for (int j = 0; j < 4; j++)
            #pragma unroll
            for (int q = 0; q < 4; q++) acc[i][j][q] = 0.f;
    const int bm = blockIdx.y * 128;
    const int bn = blockIdx.x * 128;
    tf_core(g_xa, g_winT, bm, bn, smbase, acc);

    const int wid = threadIdx.x >> 5;
    const int lane = threadIdx.x & 31;
    const int wm = (wid & 1) * 64;
    const int wn = (wid >> 1) * 32;
    const int r0 = lane >> 2;
    const int c0 = (lane & 3) * 2;
    #pragma unroll
    for (int mf = 0; mf < 4; mf++) {
        #pragma unroll
        for (int nf = 0; nf < 4; nf++) {
            const int col = bn + wn + nf * 8 + c0;
            #pragma unroll
            for (int half = 0; half < 2; half++) {
                const int row = bm + wm + mf * 16 + r0 + half * 8;
                float2 v;
                v.x = acc[mf][nf][half * 2 + 0] + bias[col];
                v.y = acc[mf][nf][half * 2 + 1] + bias[col + 1];
                *(float2*)&g_xp[(size_t)row * Cc + col] = v;
            }
        }
    }
}

// ---- GEMM 2 (tf32): g_om = x1 @ wcatT^T + bcat  (N=512 pad, store 432) -----
__global__ __launch_bounds__(256, 2)
void gemm_om() {
    extern __shared__ char smem[];
    const u32 smbase = (u32)__cvta_generic_to_shared(smem);
    float acc[4][4][4];
    #pragma unroll
    for (int i = 0; i < 4; i++)
        #pragma unroll
        for (int j = 0; j < 4; j++)
            #pragma unroll
            for (int q = 0; q < 4; q++) acc[i][j][q] = 0.f;
    const int bm = blockIdx.y * 128;
    const int bn = blockIdx.x * 128;
    tf_core(g_x1, g_wcatT, bm, bn, smbase, acc);

    const int wid = threadIdx.x >> 5;
    const int lane = threadIdx.x & 31;
    const int wm = (wid & 1) * 64;
    const int wn = (wid >> 1) * 32;
    const int r0 = lane >> 2;
    const int c0 = (lane & 3) * 2;
    #pragma unroll
    for (int mf = 0; mf < 4; mf++) {
        #pragma unroll
        for (int nf = 0; nf < 4; nf++) {
            const int col = bn + wn + nf * 8 + c0;
            if (col < Ncat) {
                #pragma unroll
                for (int half = 0; half < 2; half++) {
                    const int row = bm + wm + mf * 16 + r0 + half * 8;
                    float2 v;
                    v.x = acc[mf][nf][half * 2 + 0] + g_bcat[col];
                    v.y = acc[mf][nf][half * 2 + 1] + g_bcat[col + 1];
                    *(float2*)&g_om[(size_t)row * Ncat + col] = v;
                }
            }
        }
    }
}

// ================= bf16x3 GEMM (R7-proven) for GEMM 3 =======================
// BM=128, BN=64, BK=32, 3 stages. Stage layout (ushort):
//   A_hi [0,4096) A_lo [4096,8192) B_hi [8192,10240) B_lo [10240,12288)
#define STG_U16 12288
#define STG_B   24576
#define DSMEM_B (3 * STG_B)

__device__ __forceinline__ void pipe_issue(
    const u16* __restrict__ Ah, const u16* __restrict__ Al,
    const u16* __restrict__ Bh, const u16* __restrict__ Bl,
    int ldb, int K, int bm, int bn, int k0, u32 sb) {
    const int t = threadIdx.x;
    const int r = t >> 1;
    const int c0 = (t & 1) * 2;
    const int rx = (r >> 1) & 3;
    const size_t asrc = (size_t)(bm + r) * K + k0;
    #pragma unroll
    for (int i = 0; i < 2; i++) {
        const int c = c0 + i;
        const u32 doff = (u32)(r * 32 + ((c ^ rx) << 3)) * 2;
        cpa16(sb + doff, (const void*)(Ah + asrc + c * 8));
        cpa16(sb + 8192 + doff, (const void*)(Al + asrc + c * 8));
    }
    const int k = t >> 3;
    const int cb = t & 7;
    const u32 bdoff = (u32)(k * 64 + ((cb ^ (k & 7)) << 3)) * 2;
    const size_t bsrc = (size_t)(k0 + k) * ldb + bn + cb * 8;
    cpa16(sb + 16384 + bdoff, (const void*)(Bh + bsrc));
    cpa16(sb + 20480 + bdoff, (const void*)(Bl + bsrc));
    cpcommit();
}

__device__ __forceinline__ void pipe_compute(u32 sb, int wm, int wn, int lane,
                                             float acc[2][4][4]) {
    const int row16 = lane & 15;
    const int chi = lane >> 4;
    #pragma unroll
    for (int ks = 0; ks < 32; ks += 16) {
        u32 aH[2][4], aL[2][4];
        #pragma unroll
        for (int mt = 0; mt < 2; mt++) {
            const int row = wm + mt * 16 + row16;
            const int ch = (ks >> 3) + chi;
            const u32 aoff = (u32)(row * 32 + ((ch ^ ((row >> 1) & 3)) << 3)) * 2;
            ldmA4(aH[mt], sb + aoff);
            ldmA4(aL[mt], sb + 8192 + aoff);
        }
        u32 bH[4][2], bL[4][2];
        #pragma unroll
        for (int nt = 0; nt < 4; nt++) {
            const int k = ks + row16;
            const int cn = (wn >> 3) + nt;
            const u32 boff = (u32)(k * 64 + ((cn ^ (k & 7)) << 3)) * 2;
            ldmB2t(bH[nt], sb + 16384 + boff);
            ldmB2t(bL[nt], sb + 20480 + boff);
        }
        #pragma unroll
        for (int mt = 0; mt < 2; mt++) {
            #pragma unroll
            for (int nt = 0; nt < 4; nt++) {
                mma16816(acc[mt][nt], aH[mt], bH[nt]);
                mma16816(acc[mt][nt], aH[mt], bL[nt]);
                mma16816(acc[mt][nt], aL[mt], bH[nt]);
            }
        }
    }
}

__device__ __forceinline__ void gemm_core3(
    const u16* __restrict__ Ah, const u16* __restrict__ Al,
    const u16* __restrict__ Bh, const u16* __restrict__ Bl,
    int ldb, int K, int bm, int bn, u32 smbase, float acc[2][4][4]) {
    const int wid = threadIdx.x >> 5;
    const int lane = threadIdx.x & 31;
    const int wm = (wid >> 1) * 32;
    const int wn = (wid & 1) * 32;
    const int nkt = K / 32;
    pipe_issue(Ah, Al, Bh, Bl, ldb, K, bm, bn, 0, smbase);
    pipe_issue(Ah, Al, Bh, Bl, ldb, K, bm, bn, 32, smbase + STG_B);
    int stg = 0;
    #pragma unroll 1
    for (int kt = 0; kt < nkt; kt++) {
        if (kt == nkt - 1) cpwait0(); else cpwait1();
        __syncthreads();
        if (kt + 2 < nkt) {
            int s2 = stg + 2; if (s2 >= 3) s2 -= 3;
            pipe_issue(Ah, Al, Bh, Bl, ldb, K, bm, bn, (kt + 2) * 32,
                       smbase + (u32)s2 * STG_B);
        }
        pipe_compute(smbase + (u32)stg * STG_B, wm, wn, lane, acc);
        if (++stg == 3) stg = 0;
    }
}

// ---- GEMM 3: out = SiLU(BN(ys @ w_out + b_out)) in NCHW --------------------
__global__ __launch_bounds__(256, 2)
void gemm_out(const float* __restrict__ bias,
              const float* __restrict__ bn_g, const float* __restrict__ bn_b,
              const float* __restrict__ bn_m, const float* __restrict__ bn_v,
              float* __restrict__ out) {
    extern __shared__ char smem[];
    float acc[2][4][4];
    #pragma unroll
    for (int i = 0; i < 2; i++)
        #pragma unroll
        for (int j = 0; j < 4; j++)
            #pragma unroll
            for (int q = 0; q < 4; q++) acc[i][j][q] = 0.f;
    const int bm = blockIdx.y * 128;
    const int bnn = blockIdx.x * 64;
    const u32 smbase = (u32)__cvta_generic_to_shared(smem);
    gemm_core3(g_ysh, g_ysl, g_wouth, g_woutl, Cc, Cc, bm, bnn, smbase, acc);

    const int wid = threadIdx.x >> 5;
    const int lane = threadIdx.x & 31;
    const int wm = (wid >> 1) * 32;
    const int wn = (wid & 1) * 32;
    const int r0 = lane >> 2;
    const int c0 = (lane & 3) * 2;
    #pragma unroll
    for (int mt = 0; mt < 2; mt++) {
        #pragma unroll
        for (int nt = 0; nt < 4; nt++) {
            const int col = bnn + wn + nt * 8 + c0;
            const float s0 = bn_g[col] * rsqrtf(bn_v[col] + 1e-5f);
            const float s1 = bn_g[col + 1] * rsqrtf(bn_v[col + 1] + 1e-5f);
            #pragma unroll
            for (int half = 0; half < 2; half++) {
                const int row = bm + wm + mt * 16 + r0 + half * 8;
                const int bidx = row / HW;
                const int hw = row - bidx * HW;
                float y0 = acc[mt][nt][half * 2 + 0] + bias[col];
                float y1 = acc[mt][nt][half * 2 + 1] + bias[col + 1];
                y0 = (y0 - bn_m[col]) * s0 + bn_b[col];
                y1 = (y1 - bn_m[col + 1]) * s1 + bn_b[col + 1];
                out[((size_t)bidx * Cc + col) * HW + hw]     = y0 / (1.0f + expf(-y0));
                out[((size_t)bidx * Cc + col + 1) * HW + hw] = y1 / (1.0f + expf(-y1));
            }
        }
    }
}

// ---------------- depthwise 3x3 + LayerNorm + exact GELU -------------------
__global__ __launch_bounds__(256)
void dw_ln_gelu(const float* __restrict__ wdw, const float* __restrict__ bdw,
                const float* __restrict__ lng, const float* __restrict__ lnb) {
    __shared__ float sredA[8];
    __shared__ float sredB[8];
    const int m = blockIdx.x;
    const int b = m / HW;
    const int hw = m - b * HW;
    const int h = hw / Ww;
    const int w = hw - h * Ww;
    const int tid = threadIdx.x;
    const int wid = tid >> 5;
    const int lane = tid & 31;
    const int c = tid * 2;

    float a0 = 0.f, a1 = 0.f;
    #pragma unroll
    for (int ky = 0; ky < 3; ky++) {
        const int hy = h + ky - 1;
        if ((unsigned)hy >= (unsigned)Hh) continue;
        #pragma unroll
        for (int kx = 0; kx < 3; kx++) {
            const int wx = w + kx - 1;
            if ((unsigned)wx >= (unsigned)Ww) continue;
            const float2 v = *(const float2*)&g_xh[((size_t)(b * HW + hy * Ww + wx)) * Cc + c];
            const float2 wv = *(const float2*)&wdw[(ky * 3 + kx) * Cc + c];
            a0 = fmaf(v.x, wv.x, a0);
            a1 = fmaf(v.y, wv.y, a1);
        }
    }
    const float2 bb2 = *(const float2*)&bdw[c];
    a0 += bb2.x; a1 += bb2.y;

    float part = a0 + a1;
    #pragma unroll
    for (int s = 16; s > 0; s >>= 1) part += __shfl_xor_sync(0xffffffffu, part, s);
    if (lane == 0) sredA[wid] = part;
    __syncthreads();
    float mu = 0.f;
    #pragma unroll
    for (int i = 0; i < 8; i++) mu += sredA[i];
    mu *= (1.0f / 512.0f);

    const float d0 = a0 - mu, d1 = a1 - mu;
    float vpart = d0 * d0 + d1 * d1;
    #pragma unroll
    for (int s = 16; s > 0; s >>= 1) vpart += __shfl_xor_sync(0xffffffffu, vpart, s);
    if (lane == 0) sredB[wid] = vpart;
    __syncthreads();
    float var = 0.f;
    #pragma unroll
    for (int i = 0; i < 8; i++) var += sredB[i];
    var *= (1.0f / 512.0f);
    const float rstd = rsqrtf(var + 1e-6f);

    const float2 gg = *(const float2*)&lng[c];
    const float2 be = *(const float2*)&lnb[c];
    float o0 = d0 * rstd * gg.x + be.x;
    float o1 = d1 * rstd * gg.y + be.y;
    o0 = 0.5f * o0 * (1.0f + erff(o0 * 0.7071067811865475f));
    o1 = 0.5f * o1 * (1.0f + erff(o1 * 0.7071067811865475f));
    *(float2*)&g_x1[(size_t)m * Cc + c] = make_float2(tf32r(o0), tf32r(o1));
}

// ---------------- DCNv3 sampling + fused softmax ---------------------------
__device__ __forceinline__ float dcn_fetch(const float* __restrict__ base,
                                           int yu, int xu) {
    if ((unsigned)yu < (unsigned)Hh && (unsigned)xu < (unsigned)Ww)
        return base[(size_t)(yu * Ww + xu) * Cc];
    return 0.f;
}

__global__ __launch_bounds__(256)
void dcn_sample() {
    const int gid = blockIdx.x * 8 + (threadIdx.x >> 5);
    const int lane = threadIdx.x & 31;
    if (gid >= Mtot * Gg) return;
    const int m = gid >> 4;
    const int g = gid & 15;
    const int b = m / HW;
    const int hw = m - b * HW;
    const int h = hw / Ww;
    const int w = hw - h * Ww;

    const float rx = ((float)w + 1.5f) / 58.0f;
    const float ry = ((float)h + 1.5f) / 58.0f;

    const float* offp = g_om + (size_t)m * Ncat + g * (Pp * 2);
    const float* mskp = g_om + (size_t)m * Ncat + Noff + g * Pp;
    const float* base = g_xp + (size_t)b * HW * Cc + g * GC + lane;

    float logit[Pp];
    float mx = -1e30f;
    #pragma unroll
    for (int p = 0; p < Pp; p++) { logit[p] = mskp[p]; mx = fmaxf(mx, logit[p]); }
    float ssum = 0.f;
    #pragma unroll
    for (int p = 0; p < Pp; p++) { logit[p] = expf(logit[p] - mx); ssum += logit[p]; }
    const float sinv = 1.0f / ssum;

    float acc = 0.f;
    #pragma unroll
    for (int p = 0; p < Pp; p++) {
        const int kx = p / 3;
        const int ky = p - kx * 3;
        const float ox = offp[2 * p];
        const float oy = offp[2 * p + 1];
        const float lx = (rx + (float)(kx - 1) / 58.0f) + ox / 58.0f;
        const float ly = (ry + (float)(ky - 1) / 58.0f) + oy / 58.0f;
        const float px = lx * 58.0f - 0.5f;
        const float py = ly * 58.0f - 0.5f;
        const float x0f = floorf(px);
        const float y0f = floorf(py);
        const float txf = px - x0f;
        const float tyf = py - y0f;
        const int x0 = (int)x0f;
        const int y0 = (int)y0f;
        const float msk = logit[p] * sinv;
        const float v00 = dcn_fetch(base, y0 - 1, x0 - 1);
        const float v01 = dcn_fetch(base, y0 - 1, x0);
        const float v10 = dcn_fetch(base, y0,     x0 - 1);
        const float v11 = dcn_fetch(base, y0,     x0);
        const float s = (1.f - tyf) * (1.f - txf) * v00
                      + (1.f - tyf) * txf * v01
                      + tyf * (1.f - txf) * v10
                      + tyf * txf * v11;
        acc = fmaf(msk, s, acc);
    }
    const size_t oidx = (size_t)m * Cc + g * GC + lane;
    u16 hh, ll;
    split2u(acc, hh, ll);
    g_ysh[oidx] = hh;
    g_ysl[oidx] = ll;
}

// ---------------- host launch ----------------------------------------------
extern "C" void kernel_launch(void* const* d_in, const int* in_sizes, int n_in,
                              void* d_out, int out_size) {
    const float* x      = (const float*)d_in[0];
    const float* w_in   = (const float*)d_in[1];
    const float* b_in   = (const float*)d_in[2];
    const float* w_dw   = (const float*)d_in[3];
    const float* b_dw   = (const float*)d_in[4];
    const float* ln_g   = (const float*)d_in[5];
    const float* ln_b   = (const float*)d_in[6];
    const float* w_off  = (const float*)d_in[7];
    const float* b_off  = (const float*)d_in[8];
    const float* w_mask = (const float*)d_in[9];
    const float* b_mask = (const float*)d_in[10];
    const float* w_out  = (const float*)d_in[11];
    const float* b_out  = (const float*)d_in[12];
    const float* bn_g   = (const float*)d_in[13];
    const float* bn_b   = (const float*)d_in[14];
    const float* bn_m   = (const float*)d_in[15];
    const float* bn_v   = (const float*)d_in[16];

    float* winT;
    u16 *wouth, *woutl;
    cudaGetSymbolAddress((void**)&winT, g_winT);
    cudaGetSymbolAddress((void**)&wouth, g_wouth);
    cudaGetSymbolAddress((void**)&woutl, g_woutl);

    // one-time attribute setup (outside graph capture on first call)
    static int smem_set = 0;
    if (!smem_set) {
        cudaFuncSetAttribute(gemm_in, cudaFuncAttributeMaxDynamicSharedMemorySize, TF_DSMEM);
        cudaFuncSetAttribute(gemm_om, cudaFuncAttributeMaxDynamicSharedMemorySize, TF_DSMEM);
        cudaFuncSetAttribute(gemm_out, cudaFuncAttributeMaxDynamicSharedMemorySize, DSMEM_B);
        smem_set = 1;
    }

    // 0. weight prep
    split_w32T<<<(Cc * Cc + 255) / 256, 256>>>(w_in, winT);
    split_w<<<(Cc * Cc + 255) / 256, 256>>>(w_out, wouth, woutl, Cc * Cc);
    build_wcat32<<<(NPAD * Cc + 255) / 256, 256>>>(w_off, b_off, w_mask, b_mask);
    // 1. NCHW -> NHWC (+ tf32 copy)
    nchw_to_nhwc<<<dim3(HW / 32, Cc / 32, Bn), dim3(32, 8)>>>(x);
    // 2. input_proj (tf32 tensor cores)
    gemm_in<<<dim3(Cc / 128, Mtot / 128), 256, TF_DSMEM>>>(b_in);
    // 3. depthwise + LN + GELU (tf32-rounded out)
    dw_ln_gelu<<<Mtot, 256>>>(w_dw, b_dw, ln_g, ln_b);
    // 4. offset/mask GEMM (tf32)
    gemm_om<<<dim3(NPAD / 128, Mtot / 128), 256, TF_DSMEM>>>();
    // 5. DCN sampling (+softmax, split out)
    dcn_sample<<<(Mtot * Gg) / 8, 256>>>();
    // 6. output_proj + BN + SiLU, NCHW store (bf16x3)
    gemm_out<<<dim3(Cc / 64, Mtot / 128), 256, DSMEM_B>>>(b_out, bn_g, bn_b,
                                                          bn_m, bn_v, (float*)d_out);
}

// round 11
// speedup vs baseline: 2.0504x; 1.0550x over previous
#include <cuda_runtime.h>
#include <cuda_bf16.h>
#include <math.h>
#include <cstdint>

typedef unsigned int u32;
typedef unsigned short u16;
typedef unsigned long long u64;

// Problem constants
#define Bn 4
#define Cc 512
#define Hh 56
#define Ww 56
#define Gg 16
#define Pp 9
#define GC 32
#define HW 3136          // 56*56
#define Mtot 12544       // B*H*W
#define Noff 288         // G*P*2
#define Nmsk 144         // G*P
#define Ncat 432         // Noff+Nmsk
#define NPAD 512         // Ncat padded to 128 multiple

// ---------------- scratch (device globals; no allocation allowed) ----------
__device__ float g_xh[Mtot * Cc];        // NHWC input fp32 (for depthwise)
__device__ float g_xa[Mtot * Cc];        // tf32-rounded NHWC (GEMM1 A)
__device__ float g_xp[Mtot * Cc];        // input_proj output (for dcn)
__device__ float g_x1[Mtot * Cc];        // dw+LN+GELU, tf32-rounded (GEMM2 A)
__device__ float g_om[Mtot * Ncat];      // [offset|mask logits]
__device__ float g_ys[Mtot * Cc];        // DCN output, tf32-rounded (GEMM3 A)
__device__ float g_winT[Cc * Cc];        // w_in^T tf32-rounded: [n][k]
__device__ float g_wcatT[NPAD * Cc];     // concat weight^T tf32-rounded: [n][k]
__device__ float g_woutT[Cc * Cc];       // w_out^T tf32-rounded: [n][k]
__device__ float g_bcat[NPAD];

// ---------------- helpers ---------------------------------------------------
__device__ __forceinline__ float tf32r(float v) {
    u32 r;
    asm("cvt.rna.tf32.f32 %0, %1;" : "=r"(r) : "f"(v));
    return __uint_as_float(r);
}
__device__ __forceinline__ void ldmA4(u32* r, u32 addr) {
    asm volatile("ldmatrix.sync.aligned.m8n8.x4.shared.b16 {%0,%1,%2,%3}, [%4];\n"
                 : "=r"(r[0]), "=r"(r[1]), "=r"(r[2]), "=r"(r[3]) : "r"(addr));
}
__device__ __forceinline__ void ldmB2(u32* r, u32 addr) {
    asm volatile("ldmatrix.sync.aligned.m8n8.x2.shared.b16 {%0,%1}, [%2];\n"
                 : "=r"(r[0]), "=r"(r[1]) : "r"(addr));
}
__device__ __forceinline__ void mma_tf32(float* c, const u32* a, const u32* b) {
    asm volatile("mma.sync.aligned.m16n8k8.row.col.f32.tf32.tf32.f32 "
                 "{%0,%1,%2,%3}, {%4,%5,%6,%7}, {%8,%9}, {%0,%1,%2,%3};\n"
                 : "+f"(c[0]), "+f"(c[1]), "+f"(c[2]), "+f"(c[3])
                 : "r"(a[0]), "r"(a[1]), "r"(a[2]), "r"(a[3]), "r"(b[0]), "r"(b[1]));
}
__device__ __forceinline__ void cpa16(u32 dst, const void* src) {
    asm volatile("cp.async.cg.shared.global [%0], [%1], 16;\n" :: "r"(dst), "l"(src));
}
__device__ __forceinline__ void cpcommit() { asm volatile("cp.async.commit_group;\n"); }
__device__ __forceinline__ void cpwait0() { asm volatile("cp.async.wait_group 0;\n"); }
__device__ __forceinline__ void cpwait1() { asm volatile("cp.async.wait_group 1;\n"); }

// ---------------- weight setup ----------------------------------------------
// transpose [k][n] -> [n][k], tf32-rounded fp32
__global__ __launch_bounds__(256)
void split_w32T(const float* __restrict__ src, float* __restrict__ dst) {
    const int i = blockIdx.x * 256 + threadIdx.x;
    if (i < Cc * Cc) {
        const int k = i >> 9;
        const int n = i & 511;
        dst[n * Cc + k] = tf32r(src[i]);
    }
}
// concat offset/mask weights: [n][k] tf32-rounded, n padded to 512
__global__ __launch_bounds__(256)
void build_wcat32(const float* __restrict__ w_off, const float* __restrict__ b_off,
                  const float* __restrict__ w_mask, const float* __restrict__ b_mask) {
    const int i = blockIdx.x * 256 + threadIdx.x;
    if (i < NPAD * Cc) {
        const int n = i >> 9;
        const int k = i & 511;
        float v = 0.f;
        if (n < Noff) v = w_off[k * Noff + n];
        else if (n < Ncat) v = w_mask[k * Nmsk + (n - Noff)];
        g_wcatT[i] = tf32r(v);
    }
    if (i < NPAD)
        g_bcat[i] = (i < Noff) ? b_off[i] : (i < Ncat ? b_mask[i - Noff] : 0.f);
}

// ---------------- NCHW -> NHWC transpose (+ tf32 copy) ----------------------
__global__ __launch_bounds__(256)
void nchw_to_nhwc(const float* __restrict__ x) {
    __shared__ float tile[32][33];
    const int bb = blockIdx.z;
    const int hw0 = blockIdx.x * 32;
    const int c0 = blockIdx.y * 32;
    const int tx = threadIdx.x;
    const int ty = threadIdx.y;
    const float* xb = x + (size_t)bb * Cc * HW;
    #pragma unroll
    for (int i = 0; i < 32; i += 8)
        tile[ty + i][tx] = xb[(size_t)(c0 + ty + i) * HW + hw0 + tx];
    __syncthreads();
    #pragma unroll
    for (int i = 0; i < 32; i += 8) {
        const size_t idx = ((size_t)bb * HW + hw0 + ty + i) * Cc + c0 + tx;
        const float v = tile[tx][ty + i];
        g_xh[idx] = v;
        g_xa[idx] = tf32r(v);
    }
}

// ================= tf32 GEMM: BM=128 BN=128 BK=32, 3-stage ==================
// Stage (32768 B): A [0,16K) rows 128x128B; B [16K,32K) rows 128x128B ([n][k])
// XOR swizzle: 16B chunk c at row r -> c ^ (r&7).
#define TF_STG 32768
#define TF_DSMEM (3 * TF_STG)

__device__ __forceinline__ void tf_fill(const float* __restrict__ A,
                                        const float* __restrict__ B,
                                        int bm, int bn, int kt, u32 stg) {
    const int t = threadIdx.x;
    const int row = t >> 1;
    const int cb = (t & 1) * 4;
    const size_t ka = (size_t)(bm + row) * Cc + kt * 32;
    const size_t kb = (size_t)(bn + row) * Cc + kt * 32;
    #pragma unroll
    for (int i = 0; i < 4; i++) {
        const int c = cb + i;
        const u32 d = (u32)(row * 128 + ((c ^ (row & 7)) << 4));
        cpa16(stg + d,         (const void*)(A + ka + c * 4));
        cpa16(stg + 16384 + d, (const void*)(B + kb + c * 4));
    }
    cpcommit();
}

__device__ __forceinline__ void tf_compute(u32 stg, int wm, int wn, int lane,
                                           float acc[4][4][4]) {
    const u32 stgB = stg + 16384;
    const int arow7 = lane & 7;
    const int arow8 = ((lane >> 3) & 1) * 8;
    const int achk = lane >> 4;             // 0/1
    #pragma unroll
    for (int ks = 0; ks < 4; ks++) {
        u32 a[4][4];
        #pragma unroll
        for (int mf = 0; mf < 4; mf++) {
            const int row = wm + mf * 16 + arow7 + arow8;
            const int ch = 2 * ks + achk;
            ldmA4(a[mf], stg + (u32)(row * 128 + ((ch ^ (row & 7)) << 4)));
        }
        u32 b[4][2];
        #pragma unroll
        for (int nf = 0; nf < 4; nf++) {
            const int row = wn + nf * 8 + arow7;       // lanes 0..15 used
            const int ch = 2 * ks + ((lane >> 3) & 1);
            ldmB2(b[nf], stgB + (u32)(row * 128 + ((ch ^ (row & 7)) << 4)));
        }
        #pragma unroll
        for (int mf = 0; mf < 4; mf++)
            #pragma unroll
            for (int nf = 0; nf < 4; nf++)
                mma_tf32(acc[mf][nf], a[mf], b[nf]);
    }
}

__device__ __forceinline__ void tf_core(const float* __restrict__ A,
                                        const float* __restrict__ B,
                                        int bm, int bn, u32 smbase,
                                        float acc[4][4][4]) {
    const int wid = threadIdx.x >> 5;
    const int lane = threadIdx.x & 31;
    const int wm = (wid & 1) * 64;
    const int wn = (wid >> 1) * 32;
    const u32 st[3] = {smbase, smbase + TF_STG, smbase + 2 * TF_STG};
    tf_fill(A, B, bm, bn, 0, st[0]);
    tf_fill(A, B, bm, bn, 1, st[1]);
    #pragma unroll 1
    for (int kt = 0; kt < 16; kt++) {
        if (kt == 15) cpwait0(); else cpwait1();
        __syncthreads();
        if (kt + 2 < 16) {
            int s2 = kt + 2; s2 -= (s2 / 3) * 3;
            tf_fill(A, B, bm, bn, kt + 2, st[s2]);
        }
        int s = kt; s -= (s / 3) * 3;
        tf_compute(st[s], wm, wn, lane, acc);
    }
}

// ---- GEMM 1 (tf32): g_xp = xa @ winT^T + b_in ------------------------------
__global__ __launch_bounds__(256, 2)
void gemm_in(const float* __restrict__ bias) {
    extern __shared__ char smem[];
    const u32 smbase = (u32)__cvta_generic_to_shared(smem);
    float acc[4][4][4];
    #pragma unroll
    for (int i = 0; i < 4; i++)
        #pragma unroll
        for (int j = 0; j < 4; j++)
            #pragma unroll
            for (int q = 0; q < 4; q++) acc[i][j][q] = 0.f;
    const int bm = blockIdx.y * 128;
    const int bn = blockIdx.x * 128;
    tf_core(g_xa, g_winT, bm, bn, smbase, acc);

    const int wid = threadIdx.x >> 5;
    const int lane = threadIdx.x & 31;
    const int wm = (wid & 1) * 64;
    const int wn = (wid >> 1) * 32;
    const int r0 = lane >> 2;
    const int c0 = (lane & 3) * 2;
    #pragma unroll
    for (int mf = 0; mf < 4; mf++) {
        #pragma unroll
        for (int nf = 0; nf < 4; nf++) {
            const int col = bn + wn + nf * 8 + c0;
            #pragma unroll
            for (int half = 0; half < 2; half++) {
                const int row = bm + wm + mf * 16 + r0 + half * 8;
                float2 v;
                v.x = acc[mf][nf][half * 2 + 0] + bias[col];
                v.y = acc[mf][nf][half * 2 + 1] + bias[col + 1];
                *(float2*)&g_xp[(size_t)row * Cc + col] = v;
            }
        }
    }
}

// ---- GEMM 2 (tf32): g_om = x1 @ wcatT^T + bcat  (N=512 pad, store 432) -----
__global__ __launch_bounds__(256, 2)
void gemm_om() {
    extern __shared__ char smem[];
    const u32 smbase = (u32)__cvta_generic_to_shared(smem);
    float acc[4][4][4];
    #pragma unroll
    for (int i = 0; i < 4; i++)
        #pragma unroll
        for (int j = 0; j < 4; j++)
            #pragma unroll
            for (int q = 0; q < 4; q++) acc[i][j][q] = 0.f;
    const int bm = blockIdx.y * 128;
    const int bn = blockIdx.x * 128;
    tf_core(g_x1, g_wcatT, bm, bn, smbase, acc);

    const int wid = threadIdx.x >> 5;
    const int lane = threadIdx.x & 31;
    const int wm = (wid & 1) * 64;
    const int wn = (wid >> 1) * 32;
    const int r0 = lane >> 2;
    const int c0 = (lane & 3) * 2;
    #pragma unroll
    for (int mf = 0; mf < 4; mf++) {
        #pragma unroll
        for (int nf = 0; nf < 4; nf++) {
            const int col = bn + wn + nf * 8 + c0;
            if (col < Ncat) {
                #pragma unroll
                for (int half = 0; half < 2; half++) {
                    const int row = bm + wm + mf * 16 + r0 + half * 8;
                    float2 v;
                    v.x = acc[mf][nf][half * 2 + 0] + g_bcat[col];
                    v.y = acc[mf][nf][half * 2 + 1] + g_bcat[col + 1];
                    *(float2*)&g_om[(size_t)row * Ncat + col] = v;
                }
            }
        }
    }
}

// ---- GEMM 3 (tf32): out = SiLU(BN(ys @ woutT^T + b_out)) in NCHW -----------
__global__ __launch_bounds__(256, 2)
void gemm_out(const float* __restrict__ bias,
              const float* __restrict__ bn_g, const float* __restrict__ bn_b,
              const float* __restrict__ bn_m, const float* __restrict__ bn_v,
              float* __restrict__ out) {
    extern __shared__ char smem[];
    const u32 smbase = (u32)__cvta_generic_to_shared(smem);
    float acc[4][4][4];
    #pragma unroll
    for (int i = 0; i < 4; i++)
        #pragma unroll
        for (int j = 0; j < 4; j++)
            #pragma unroll
            for (int q = 0; q < 4; q++) acc[i][j][q] = 0.f;
    const int bm = blockIdx.y * 128;
    const int bn = blockIdx.x * 128;
    tf_core(g_ys, g_woutT, bm, bn, smbase, acc);

    const int wid = threadIdx.x >> 5;
    const int lane = threadIdx.x & 31;
    const int wm = (wid & 1) * 64;
    const int wn = (wid >> 1) * 32;
    const int r0 = lane >> 2;
    const int c0 = (lane & 3) * 2;
    #pragma unroll
    for (int mf = 0; mf < 4; mf++) {
        #pragma unroll
        for (int nf = 0; nf < 4; nf++) {
            const int col = bn + wn + nf * 8 + c0;
            const float s0 = bn_g[col] * rsqrtf(bn_v[col] + 1e-5f);
            const float s1 = bn_g[col + 1] * rsqrtf(bn_v[col + 1] + 1e-5f);
            #pragma unroll
            for (int half = 0; half < 2; half++) {
                const int row = bm + wm + mf * 16 + r0 + half * 8;
                const int bidx = row / HW;
                const int hw = row - bidx * HW;
                float y0 = acc[mf][nf][half * 2 + 0] + bias[col];
                float y1 = acc[mf][nf][half * 2 + 1] + bias[col + 1];
                y0 = (y0 - bn_m[col]) * s0 + bn_b[col];
                y1 = (y1 - bn_m[col + 1]) * s1 + bn_b[col + 1];
                out[((size_t)bidx * Cc + col) * HW + hw]     = y0 / (1.0f + expf(-y0));
                out[((size_t)bidx * Cc + col + 1) * HW + hw] = y1 / (1.0f + expf(-y1));
            }
        }
    }
}

// ---------------- depthwise 3x3 + LayerNorm + exact GELU -------------------
__global__ __launch_bounds__(256)
void dw_ln_gelu(const float* __restrict__ wdw, const float* __restrict__ bdw,
                const float* __restrict__ lng, const float* __restrict__ lnb) {
    __shared__ float sredA[8];
    __shared__ float sredB[8];
    const int m = blockIdx.x;
    const int b = m / HW;
    const int hw = m - b * HW;
    const int h = hw / Ww;
    const int w = hw - h * Ww;
    const int tid = threadIdx.x;
    const int wid = tid >> 5;
    const int lane = tid & 31;
    const int c = tid * 2;

    float a0 = 0.f, a1 = 0.f;
    #pragma unroll
    for (int ky = 0; ky < 3; ky++) {
        const int hy = h + ky - 1;
        if ((unsigned)hy >= (unsigned)Hh) continue;
        #pragma unroll
        for (int kx = 0; kx < 3; kx++) {
            const int wx = w + kx - 1;
            if ((unsigned)wx >= (unsigned)Ww) continue;
            const float2 v = *(const float2*)&g_xh[((size_t)(b * HW + hy * Ww + wx)) * Cc + c];
            const float2 wv = *(const float2*)&wdw[(ky * 3 + kx) * Cc + c];
            a0 = fmaf(v.x, wv.x, a0);
            a1 = fmaf(v.y, wv.y, a1);
        }
    }
    const float2 bb2 = *(const float2*)&bdw[c];
    a0 += bb2.x; a1 += bb2.y;

    float part = a0 + a1;
    #pragma unroll
    for (int s = 16; s > 0; s >>= 1) part += __shfl_xor_sync(0xffffffffu, part, s);
    if (lane == 0) sredA[wid] = part;
    __syncthreads();
    float mu = 0.f;
    #pragma unroll
    for (int i = 0; i < 8; i++) mu += sredA[i];
    mu *= (1.0f / 512.0f);

    const float d0 = a0 - mu, d1 = a1 - mu;
    float vpart = d0 * d0 + d1 * d1;
    #pragma unroll
    for (int s = 16; s > 0; s >>= 1) vpart += __shfl_xor_sync(0xffffffffu, vpart, s);
    if (lane == 0) sredB[wid] = vpart;
    __syncthreads();
    float var = 0.f;
    #pragma unroll
    for (int i = 0; i < 8; i++) var += sredB[i];
    var *= (1.0f / 512.0f);
    const float rstd = rsqrtf(var + 1e-6f);

    const float2 gg = *(const float2*)&lng[c];
    const float2 be = *(const float2*)&lnb[c];
    float o0 = d0 * rstd * gg.x + be.x;
    float o1 = d1 * rstd * gg.y + be.y;
    o0 = 0.5f * o0 * (1.0f + erff(o0 * 0.7071067811865475f));
    o1 = 0.5f * o1 * (1.0f + erff(o1 * 0.7071067811865475f));
    *(float2*)&g_x1[(size_t)m * Cc + c] = make_float2(tf32r(o0), tf32r(o1));
}

// ---------------- DCNv3 sampling + fused softmax ---------------------------
__device__ __forceinline__ float dcn_fetch(const float* __restrict__ base,
                                           int yu, int xu) {
    if ((unsigned)yu < (unsigned)Hh && (unsigned)xu < (unsigned)Ww)
        return base[(size_t)(yu * Ww + xu) * Cc];
    return 0.f;
}

__global__ __launch_bounds__(256)
void dcn_sample() {
    const int gid = blockIdx.x * 8 + (threadIdx.x >> 5);
    const int lane = threadIdx.x & 31;
    if (gid >= Mtot * Gg) return;
    const int m = gid >> 4;
    const int g = gid & 15;
    const int b = m / HW;
    const int hw = m - b * HW;
    const int h = hw / Ww;
    const int w = hw - h * Ww;

    const float rx = ((float)w + 1.5f) / 58.0f;
    const float ry = ((float)h + 1.5f) / 58.0f;

    const float* offp = g_om + (size_t)m * Ncat + g * (Pp * 2);
    const float* mskp = g_om + (size_t)m * Ncat + Noff + g * Pp;
    const float* base = g_xp + (size_t)b * HW * Cc + g * GC + lane;

    float logit[Pp];
    float mx = -1e30f;
    #pragma unroll
    for (int p = 0; p < Pp; p++) { logit[p] = mskp[p]; mx = fmaxf(mx, logit[p]); }
    float ssum = 0.f;
    #pragma unroll
    for (int p = 0; p < Pp; p++) { logit[p] = expf(logit[p] - mx); ssum += logit[p]; }
    const float sinv = 1.0f / ssum;

    float acc = 0.f;
    #pragma unroll
    for (int p = 0; p < Pp; p++) {
        const int kx = p / 3;
        const int ky = p - kx * 3;
        const float ox = offp[2 * p];
        const float oy = offp[2 * p + 1];
        const float lx = (rx + (float)(kx - 1) / 58.0f) + ox / 58.0f;
        const float ly = (ry + (float)(ky - 1) / 58.0f) + oy / 58.0f;
        const float px = lx * 58.0f - 0.5f;
        const float py = ly * 58.0f - 0.5f;
        const float x0f = floorf(px);
        const float y0f = floorf(py);
        const float txf = px - x0f;
        const float tyf = py - y0f;
        const int x0 = (int)x0f;
        const int y0 = (int)y0f;
        const float msk = logit[p] * sinv;
        const float v00 = dcn_fetch(base, y0 - 1, x0 - 1);
        const float v01 = dcn_fetch(base, y0 - 1, x0);
        const float v10 = dcn_fetch(base, y0,     x0 - 1);
        const float v11 = dcn_fetch(base, y0,     x0);
        const float s = (1.f - tyf) * (1.f - txf) * v00
                      + (1.f - tyf) * txf * v01
                      + tyf * (1.f - txf) * v10
                      + tyf * txf * v11;
        acc = fmaf(msk, s, acc);
    }
    g_ys[(size_t)m * Cc + g * GC + lane] = tf32r(acc);
}

// ---------------- host launch ----------------------------------------------
extern "C" void kernel_launch(void* const* d_in, const int* in_sizes, int n_in,
                              void* d_out, int out_size) {
    const float* x      = (const float*)d_in[0];
    const float* w_in   = (const float*)d_in[1];
    const float* b_in   = (const float*)d_in[2];
    const float* w_dw   = (const float*)d_in[3];
    const float* b_dw   = (const float*)d_in[4];
    const float* ln_g   = (const float*)d_in[5];
    const float* ln_b   = (const float*)d_in[6];
    const float* w_off  = (const float*)d_in[7];
    const float* b_off  = (const float*)d_in[8];
    const float* w_mask = (const float*)d_in[9];
    const float* b_mask = (const float*)d_in[10];
    const float* w_out  = (const float*)d_in[11];
    const float* b_out  = (const float*)d_in[12];
    const float* bn_g   = (const float*)d_in[13];
    const float* bn_b   = (const float*)d_in[14];
    const float* bn_m   = (const float*)d_in[15];
    const float* bn_v   = (const float*)d_in[16];

    float *winT, *woutT;
    cudaGetSymbolAddress((void**)&winT, g_winT);
    cudaGetSymbolAddress((void**)&woutT, g_woutT);

    // one-time setup (first call is the uncaptured correctness run)
    static int inited = 0;
    static cudaStream_t s1;
    static cudaEvent_t evS, evT, evP, ev2;
    if (!inited) {
        cudaFuncSetAttribute(gemm_in, cudaFuncAttributeMaxDynamicSharedMemorySize, TF_DSMEM);
        cudaFuncSetAttribute(gemm_om, cudaFuncAttributeMaxDynamicSharedMemorySize, TF_DSMEM);
        cudaFuncSetAttribute(gemm_out, cudaFuncAttributeMaxDynamicSharedMemorySize, TF_DSMEM);
        cudaStreamCreateWithFlags(&s1, cudaStreamNonBlocking);
        cudaEventCreateWithFlags(&evS, cudaEventDisableTiming);
        cudaEventCreateWithFlags(&evT, cudaEventDisableTiming);
        cudaEventCreateWithFlags(&evP, cudaEventDisableTiming);
        cudaEventCreateWithFlags(&ev2, cudaEventDisableTiming);
        inited = 1;
    }

    // fork s1 from the main (capture) stream
    cudaEventRecord(evS, 0);
    cudaStreamWaitEvent(s1, evS, 0);

    // s1: weight prep (independent of input transpose)
    split_w32T<<<(Cc * Cc + 255) / 256, 256, 0, s1>>>(w_in, winT);
    split_w32T<<<(Cc * Cc + 255) / 256, 256, 0, s1>>>(w_out, woutT);
    build_wcat32<<<(NPAD * Cc + 255) / 256, 256, 0, s1>>>(w_off, b_off, w_mask, b_mask);
    cudaEventRecord(evP, s1);

    // s0: NCHW -> NHWC (+ tf32 copy)
    nchw_to_nhwc<<<dim3(HW / 32, Cc / 32, Bn), dim3(32, 8)>>>(x);
    cudaEventRecord(evT, 0);

    // s1: depthwise branch + offset/mask GEMM (after transpose)
    cudaStreamWaitEvent(s1, evT, 0);
    dw_ln_gelu<<<Mtot, 256, 0, s1>>>(w_dw, b_dw, ln_g, ln_b);
    gemm_om<<<dim3(NPAD / 128, Mtot / 128), 256, TF_DSMEM, s1>>>();
    cudaEventRecord(ev2, s1);

    // s0: input_proj (after weight prep) — overlaps with dw+gemm_om on s1
    cudaStreamWaitEvent(0, evP, 0);
    gemm_in<<<dim3(Cc / 128, Mtot / 128), 256, TF_DSMEM>>>(b_in);

    // join: dcn needs xp (s0) + om (s1)
    cudaStreamWaitEvent(0, ev2, 0);
    dcn_sample<<<(Mtot * Gg) / 8, 256>>>();
    // output_proj + BN + SiLU (tf32)
    gemm_out<<<dim3(Cc / 128, Mtot / 128), 256, TF_DSMEM>>>(b_out, bn_g, bn_b,
                                                            bn_m, bn_v, (float*)d_out);
}

// round 12
// speedup vs baseline: 2.3250x; 1.1339x over previous
#include <cuda_runtime.h>
#include <cuda_bf16.h>
#include <math.h>
#include <cstdint>

typedef unsigned int u32;
typedef unsigned short u16;
typedef unsigned long long u64;

// Problem constants
#define Bn 4
#define Cc 512
#define Hh 56
#define Ww 56
#define Gg 16
#define Pp 9
#define GC 32
#define HW 3136          // 56*56
#define Mtot 12544       // B*H*W
#define Noff 288         // G*P*2
#define Nmsk 144         // G*P
#define Ncat 432         // Noff+Nmsk
#define NPAD 512         // Ncat padded to 128 multiple

// ---------------- scratch (device globals; no allocation allowed) ----------
__device__ float g_xh[Mtot * Cc];        // NHWC input fp32 (for depthwise)
__device__ float g_xa[Mtot * Cc];        // tf32-rounded NHWC (GEMM1 A)
__device__ float g_xp[Mtot * Cc];        // input_proj output (for dcn)
__device__ float g_x1[Mtot * Cc];        // dw+LN+GELU, tf32-rounded (GEMM2 A)
__device__ float g_om[Mtot * Ncat];      // [offset|mask logits]
__device__ float g_ys[Mtot * Cc];        // DCN output, tf32-rounded (GEMM3 A)
__device__ float g_winT[Cc * Cc];        // w_in^T tf32-rounded: [n][k]
__device__ float g_wcatT[NPAD * Cc];     // concat weight^T tf32-rounded: [n][k]
__device__ float g_woutT[Cc * Cc];       // w_out^T tf32-rounded: [n][k]
__device__ float g_bcat[NPAD];

// ---------------- helpers ---------------------------------------------------
__device__ __forceinline__ float tf32r(float v) {
    u32 r;
    asm("cvt.rna.tf32.f32 %0, %1;" : "=r"(r) : "f"(v));
    return __uint_as_float(r);
}
__device__ __forceinline__ void ldmA4(u32* r, u32 addr) {
    asm volatile("ldmatrix.sync.aligned.m8n8.x4.shared.b16 {%0,%1,%2,%3}, [%4];\n"
                 : "=r"(r[0]), "=r"(r[1]), "=r"(r[2]), "=r"(r[3]) : "r"(addr));
}
__device__ __forceinline__ void ldmB2(u32* r, u32 addr) {
    asm volatile("ldmatrix.sync.aligned.m8n8.x2.shared.b16 {%0,%1}, [%2];\n"
                 : "=r"(r[0]), "=r"(r[1]) : "r"(addr));
}
__device__ __forceinline__ void mma_tf32(float* c, const u32* a, const u32* b) {
    asm volatile("mma.sync.aligned.m16n8k8.row.col.f32.tf32.tf32.f32 "
                 "{%0,%1,%2,%3}, {%4,%5,%6,%7}, {%8,%9}, {%0,%1,%2,%3};\n"
                 : "+f"(c[0]), "+f"(c[1]), "+f"(c[2]), "+f"(c[3])
                 : "r"(a[0]), "r"(a[1]), "r"(a[2]), "r"(a[3]), "r"(b[0]), "r"(b[1]));
}
__device__ __forceinline__ void cpa16(u32 dst, const void* src) {
    asm volatile("cp.async.cg.shared.global [%0], [%1], 16;\n" :: "r"(dst), "l"(src));
}
__device__ __forceinline__ void cpcommit() { asm volatile("cp.async.commit_group;\n"); }
__device__ __forceinline__ void cpwait0() { asm volatile("cp.async.wait_group 0;\n"); }
__device__ __forceinline__ void cpwait1() { asm volatile("cp.async.wait_group 1;\n"); }

// ---------------- fused weight prep -----------------------------------------
// Three 262144-element jobs: winT, woutT, wcatT(+bcat). 1024 blocks each.
__global__ __launch_bounds__(256)
void prep_weights(const float* __restrict__ w_in, const float* __restrict__ w_out,
                  const float* __restrict__ w_off, const float* __restrict__ b_off,
                  const float* __restrict__ w_mask, const float* __restrict__ b_mask) {
    const int seg = blockIdx.x >> 10;
    const int i = ((blockIdx.x & 1023) << 8) + threadIdx.x;
    if (seg == 0) {
        const int k = i >> 9;
        const int n = i & 511;
        g_winT[n * Cc + k] = tf32r(w_in[i]);
    } else if (seg == 1) {
        const int k = i >> 9;
        const int n = i & 511;
        g_woutT[n * Cc + k] = tf32r(w_out[i]);
    } else {
        const int n = i >> 9;
        const int k = i & 511;
        float v = 0.f;
        if (n < Noff) v = w_off[k * Noff + n];
        else if (n < Ncat) v = w_mask[k * Nmsk + (n - Noff)];
        g_wcatT[i] = tf32r(v);
        if (i < NPAD)
            g_bcat[i] = (i < Noff) ? b_off[i] : (i < Ncat ? b_mask[i - Noff] : 0.f);
    }
}

// ---------------- NCHW -> NHWC transpose (+ tf32 copy) ----------------------
__global__ __launch_bounds__(256)
void nchw_to_nhwc(const float* __restrict__ x) {
    __shared__ float tile[32][33];
    const int bb = blockIdx.z;
    const int hw0 = blockIdx.x * 32;
    const int c0 = blockIdx.y * 32;
    const int tx = threadIdx.x;
    const int ty = threadIdx.y;
    const float* xb = x + (size_t)bb * Cc * HW;
    #pragma unroll
    for (int i = 0; i < 32; i += 8)
        tile[ty + i][tx] = xb[(size_t)(c0 + ty + i) * HW + hw0 + tx];
    __syncthreads();
    #pragma unroll
    for (int i = 0; i < 32; i += 8) {
        const size_t idx = ((size_t)bb * HW + hw0 + ty + i) * Cc + c0 + tx;
        const float v = tile[tx][ty + i];
        g_xh[idx] = v;
        g_xa[idx] = tf32r(v);
    }
}

// ================= tf32 GEMM: BM=128 BN=128 BK=32, 3-stage ==================
#define TF_STG 32768
#define TF_DSMEM (3 * TF_STG)

__device__ __forceinline__ void tf_fill(const float* __restrict__ A,
                                        const float* __restrict__ B,
                                        int bm, int bn, int kt, u32 stg) {
    const int t = threadIdx.x;
    const int row = t >> 1;
    const int cb = (t & 1) * 4;
    const size_t ka = (size_t)(bm + row) * Cc + kt * 32;
    const size_t kb = (size_t)(bn + row) * Cc + kt * 32;
    #pragma unroll
    for (int i = 0; i < 4; i++) {
        const int c = cb + i;
        const u32 d = (u32)(row * 128 + ((c ^ (row & 7)) << 4));
        cpa16(stg + d,         (const void*)(A + ka + c * 4));
        cpa16(stg + 16384 + d, (const void*)(B + kb + c * 4));
    }
    cpcommit();
}

__device__ __forceinline__ void tf_compute(u32 stg, int wm, int wn, int lane,
                                           float acc[4][4][4]) {
    const u32 stgB = stg + 16384;
    const int arow7 = lane & 7;
    const int arow8 = ((lane >> 3) & 1) * 8;
    const int achk = lane >> 4;
    #pragma unroll
    for (int ks = 0; ks < 4; ks++) {
        u32 a[4][4];
        #pragma unroll
        for (int mf = 0; mf < 4; mf++) {
            const int row = wm + mf * 16 + arow7 + arow8;
            const int ch = 2 * ks + achk;
            ldmA4(a[mf], stg + (u32)(row * 128 + ((ch ^ (row & 7)) << 4)));
        }
        u32 b[4][2];
        #pragma unroll
        for (int nf = 0; nf < 4; nf++) {
            const int row = wn + nf * 8 + arow7;
            const int ch = 2 * ks + ((lane >> 3) & 1);
            ldmB2(b[nf], stgB + (u32)(row * 128 + ((ch ^ (row & 7)) << 4)));
        }
        #pragma unroll
        for (int mf = 0; mf < 4; mf++)
            #pragma unroll
            for (int nf = 0; nf < 4; nf++)
                mma_tf32(acc[mf][nf], a[mf], b[nf]);
    }
}

__device__ __forceinline__ void tf_core(const float* __restrict__ A,
                                        const float* __restrict__ B,
                                        int bm, int bn, u32 smbase,
                                        float acc[4][4][4]) {
    const int wid = threadIdx.x >> 5;
    const int lane = threadIdx.x & 31;
    const int wm = (wid & 1) * 64;
    const int wn = (wid >> 1) * 32;
    const u32 st[3] = {smbase, smbase + TF_STG, smbase + 2 * TF_STG};
    tf_fill(A, B, bm, bn, 0, st[0]);
    tf_fill(A, B, bm, bn, 1, st[1]);
    #pragma unroll 1
    for (int kt = 0; kt < 16; kt++) {
        if (kt == 15) cpwait0(); else cpwait1();
        __syncthreads();
        if (kt + 2 < 16) {
            int s2 = kt + 2; s2 -= (s2 / 3) * 3;
            tf_fill(A, B, bm, bn, kt + 2, st[s2]);
        }
        int s = kt; s -= (s / 3) * 3;
        tf_compute(st[s], wm, wn, lane, acc);
    }
}

// ---- GEMM 1 (tf32): g_xp = xa @ winT^T + b_in ------------------------------
__global__ __launch_bounds__(256, 2)
void gemm_in(const float* __restrict__ bias) {
    extern __shared__ char smem[];
    const u32 smbase = (u32)__cvta_generic_to_shared(smem);
    float acc[4][4][4];
    #pragma unroll
    for (int i = 0; i < 4; i++)
        #pragma unroll
        for (int j = 0; j < 4; j++)
            #pragma unroll
            for (int q = 0; q < 4; q++) acc[i][j][q] = 0.f;
    const int bm = blockIdx.y * 128;
    const int bn = blockIdx.x * 128;
    tf_core(g_xa, g_winT, bm, bn, smbase, acc);

    const int wid = threadIdx.x >> 5;
    const int lane = threadIdx.x & 31;
    const int wm = (wid & 1) * 64;
    const int wn = (wid >> 1) * 32;
    const int r0 = lane >> 2;
    const int c0 = (lane & 3) * 2;
    #pragma unroll
    for (int mf = 0; mf < 4; mf++) {
        #pragma unroll
        for (int nf = 0; nf < 4; nf++) {
            const int col = bn + wn + nf * 8 + c0;
            #pragma unroll
            for (int half = 0; half < 2; half++) {
                const int row = bm + wm + mf * 16 + r0 + half * 8;
                float2 v;
                v.x = acc[mf][nf][half * 2 + 0] + bias[col];
                v.y = acc[mf][nf][half * 2 + 1] + bias[col + 1];
                *(float2*)&g_xp[(size_t)row * Cc + col] = v;
            }
        }
    }
}

// ---- GEMM 2 (tf32): g_om = x1 @ wcatT^T + bcat  (N=512 pad, store 432) -----
__global__ __launch_bounds__(256, 2)
void gemm_om() {
    extern __shared__ char smem[];
    const u32 smbase = (u32)__cvta_generic_to_shared(smem);
    float acc[4][4][4];
    #pragma unroll
    for (int i = 0; i < 4; i++)
        #pragma unroll
        for (int j = 0; j < 4; j++)
            #pragma unroll
            for (int q = 0; q < 4; q++) acc[i][j][q] = 0.f;
    const int bm = blockIdx.y * 128;
    const int bn = blockIdx.x * 128;
    tf_core(g_x1, g_wcatT, bm, bn, smbase, acc);

    const int wid = threadIdx.x >> 5;
    const int lane = threadIdx.x & 31;
    const int wm = (wid & 1) * 64;
    const int wn = (wid >> 1) * 32;
    const int r0 = lane >> 2;
    const int c0 = (lane & 3) * 2;
    #pragma unroll
    for (int mf = 0; mf < 4; mf++) {
        #pragma unroll
        for (int nf = 0; nf < 4; nf++) {
            const int col = bn + wn + nf * 8 + c0;
            if (col < Ncat) {
                #pragma unroll
                for (int half = 0; half < 2; half++) {
                    const int row = bm + wm + mf * 16 + r0 + half * 8;
                    float2 v;
                    v.x = acc[mf][nf][half * 2 + 0] + g_bcat[col];
                    v.y = acc[mf][nf][half * 2 + 1] + g_bcat[col + 1];
                    *(float2*)&g_om[(size_t)row * Ncat + col] = v;
                }
            }
        }
    }
}

// ---- GEMM 3 (tf32): out = SiLU(BN(ys @ woutT^T + b_out)) in NCHW -----------
__global__ __launch_bounds__(256, 2)
void gemm_out(const float* __restrict__ bias,
              const float* __restrict__ bn_g, const float* __restrict__ bn_b,
              const float* __restrict__ bn_m, const float* __restrict__ bn_v,
              float* __restrict__ out) {
    extern __shared__ char smem[];
    const u32 smbase = (u32)__cvta_generic_to_shared(smem);
    float acc[4][4][4];
    #pragma unroll
    for (int i = 0; i < 4; i++)
        #pragma unroll
        for (int j = 0; j < 4; j++)
            #pragma unroll
            for (int q = 0; q < 4; q++) acc[i][j][q] = 0.f;
    const int bm = blockIdx.y * 128;
    const int bn = blockIdx.x * 128;
    tf_core(g_ys, g_woutT, bm, bn, smbase, acc);

    const int wid = threadIdx.x >> 5;
    const int lane = threadIdx.x & 31;
    const int wm = (wid & 1) * 64;
    const int wn = (wid >> 1) * 32;
    const int r0 = lane >> 2;
    const int c0 = (lane & 3) * 2;
    #pragma unroll
    for (int mf = 0; mf < 4; mf++) {
        #pragma unroll
        for (int nf = 0; nf < 4; nf++) {
            const int col = bn + wn + nf * 8 + c0;
            const float s0 = bn_g[col] * rsqrtf(bn_v[col] + 1e-5f);
            const float s1 = bn_g[col + 1] * rsqrtf(bn_v[col + 1] + 1e-5f);
            #pragma unroll
            for (int half = 0; half < 2; half++) {
                const int row = bm + wm + mf * 16 + r0 + half * 8;
                const int bidx = row / HW;
                const int hw = row - bidx * HW;
                float y0 = acc[mf][nf][half * 2 + 0] + bias[col];
                float y1 = acc[mf][nf][half * 2 + 1] + bias[col + 1];
                y0 = (y0 - bn_m[col]) * s0 + bn_b[col];
                y1 = (y1 - bn_m[col + 1]) * s1 + bn_b[col + 1];
                out[((size_t)bidx * Cc + col) * HW + hw]     = y0 / (1.0f + expf(-y0));
                out[((size_t)bidx * Cc + col + 1) * HW + hw] = y1 / (1.0f + expf(-y1));
            }
        }
    }
}

// ------- depthwise 3x3 + LN + GELU: 8-pixel sliding window per block -------
__global__ __launch_bounds__(256)
void dw_ln_gelu(const float* __restrict__ wdw, const float* __restrict__ bdw,
                const float* __restrict__ lng, const float* __restrict__ lnb) {
    __shared__ float sA[8][8];   // [warp][px]
    __shared__ float sB[8][8];
    const int m0 = blockIdx.x * 8;        // 8 consecutive pixels, same row
    const int b = m0 / HW;
    const int hw0 = m0 - b * HW;
    const int h = hw0 / Ww;
    const int w0 = hw0 - h * Ww;          // multiple of 8 (56 % 8 == 0)
    const int tid = threadIdx.x;
    const int wid = tid >> 5;
    const int lane = tid & 31;
    const int c = tid * 2;

    float a0[8], a1[8];
    #pragma unroll
    for (int i = 0; i < 8; i++) { a0[i] = 0.f; a1[i] = 0.f; }

    #pragma unroll
    for (int ky = 0; ky < 3; ky++) {
        const int hy = h + ky - 1;
        if ((unsigned)hy >= (unsigned)Hh) continue;
        const float2 wv0 = *(const float2*)&wdw[(ky * 3 + 0) * Cc + c];
        const float2 wv1 = *(const float2*)&wdw[(ky * 3 + 1) * Cc + c];
        const float2 wv2 = *(const float2*)&wdw[(ky * 3 + 2) * Cc + c];
        float2 rv[10];
        #pragma unroll
        for (int j = 0; j < 10; j++) {
            const int wx = w0 + j - 1;
            if ((unsigned)wx < (unsigned)Ww)
                rv[j] = *(const float2*)&g_xh[((size_t)(b * HW + hy * Ww + wx)) * Cc + c];
            else
                rv[j] = make_float2(0.f, 0.f);
        }
        #pragma unroll
        for (int px = 0; px < 8; px++) {
            a0[px] = fmaf(rv[px].x,     wv0.x, a0[px]);
            a1[px] = fmaf(rv[px].y,     wv0.y, a1[px]);
            a0[px] = fmaf(rv[px + 1].x, wv1.x, a0[px]);
            a1[px] = fmaf(rv[px + 1].y, wv1.y, a1[px]);
            a0[px] = fmaf(rv[px + 2].x, wv2.x, a0[px]);
            a1[px] = fmaf(rv[px + 2].y, wv2.y, a1[px]);
        }
    }
    const float2 bb2 = *(const float2*)&bdw[c];
    #pragma unroll
    for (int px = 0; px < 8; px++) { a0[px] += bb2.x; a1[px] += bb2.y; }

    // mean per pixel
    #pragma unroll
    for (int px = 0; px < 8; px++) {
        float part = a0[px] + a1[px];
        #pragma unroll
        for (int s = 16; s > 0; s >>= 1) part += __shfl_xor_sync(0xffffffffu, part, s);
        if (lane == 0) sA[wid][px] = part;
    }
    __syncthreads();
    float mu[8];
    #pragma unroll
    for (int px = 0; px < 8; px++) {
        float s = 0.f;
        #pragma unroll
        for (int i = 0; i < 8; i++) s += sA[i][px];
        mu[px] = s * (1.0f / 512.0f);
    }
    // variance per pixel
    #pragma unroll
    for (int px = 0; px < 8; px++) {
        const float d0 = a0[px] - mu[px];
        const float d1 = a1[px] - mu[px];
        float vp = d0 * d0 + d1 * d1;
        #pragma unroll
        for (int s = 16; s > 0; s >>= 1) vp += __shfl_xor_sync(0xffffffffu, vp, s);
        if (lane == 0) sB[wid][px] = vp;
    }
    __syncthreads();

    const float2 gg = *(const float2*)&lng[c];
    const float2 be = *(const float2*)&lnb[c];
    #pragma unroll
    for (int px = 0; px < 8; px++) {
        float var = 0.f;
        #pragma unroll
        for (int i = 0; i < 8; i++) var += sB[i][px];
        var *= (1.0f / 512.0f);
        const float rstd = rsqrtf(var + 1e-6f);
        float o0 = (a0[px] - mu[px]) * rstd * gg.x + be.x;
        float o1 = (a1[px] - mu[px]) * rstd * gg.y + be.y;
        o0 = 0.5f * o0 * (1.0f + erff(o0 * 0.7071067811865475f));
        o1 = 0.5f * o1 * (1.0f + erff(o1 * 0.7071067811865475f));
        *(float2*)&g_x1[(size_t)(m0 + px) * Cc + c] = make_float2(tf32r(o0), tf32r(o1));
    }
}

// ---------------- DCNv3 sampling + fused softmax ---------------------------
__device__ __forceinline__ float dcn_fetch(const float* __restrict__ base,
                                           int yu, int xu) {
    if ((unsigned)yu < (unsigned)Hh && (unsigned)xu < (unsigned)Ww)
        return base[(size_t)(yu * Ww + xu) * Cc];
    return 0.f;
}

__global__ __launch_bounds__(256)
void dcn_sample() {
    const int gid = blockIdx.x * 8 + (threadIdx.x >> 5);
    const int lane = threadIdx.x & 31;
    if (gid >= Mtot * Gg) return;
    const int m = gid >> 4;
    const int g = gid & 15;
    const int b = m / HW;
    const int hw = m - b * HW;
    const int h = hw / Ww;
    const int w = hw - h * Ww;

    const float* offp = g_om + (size_t)m * Ncat + g * (Pp * 2);
    const float* mskp = g_om + (size_t)m * Ncat + Noff + g * Pp;
    const float* base = g_xp + (size_t)b * HW * Cc + g * GC + lane;

    float logit[Pp];
    float mx = -1e30f;
    #pragma unroll
    for (int p = 0; p < Pp; p++) { logit[p] = mskp[p]; mx = fmaxf(mx, logit[p]); }
    float ssum = 0.f;
    #pragma unroll
    for (int p = 0; p < Pp; p++) { logit[p] = expf(logit[p] - mx); ssum += logit[p]; }
    const float sinv = 1.0f / ssum;

    float acc = 0.f;
    #pragma unroll
    for (int p = 0; p < Pp; p++) {
        const int kx = p / 3;
        const int ky = p - kx * 3;
        const float2 o2 = *(const float2*)&offp[2 * p];
        // unpadded sampling coords; floor/frac identical to reference chain
        const float fx = (float)(w + kx - 1) + o2.x;
        const float fy = (float)(h + ky - 1) + o2.y;
        const float x0f = floorf(fx);
        const float y0f = floorf(fy);
        const float txf = fx - x0f;
        const float tyf = fy - y0f;
        const int x0 = (int)x0f;
        const int y0 = (int)y0f;
        const float msk = logit[p] * sinv;
        const float v00 = dcn_fetch(base, y0,     x0);
        const float v01 = dcn_fetch(base, y0,     x0 + 1);
        const float v10 = dcn_fetch(base, y0 + 1, x0);
        const float v11 = dcn_fetch(base, y0 + 1, x0 + 1);
        const float s = (1.f - tyf) * (1.f - txf) * v00
                      + (1.f - tyf) * txf * v01
                      + tyf * (1.f - txf) * v10
                      + tyf * txf * v11;
        acc = fmaf(msk, s, acc);
    }
    g_ys[(size_t)m * Cc + g * GC + lane] = tf32r(acc);
}

// ---------------- host launch ----------------------------------------------
extern "C" void kernel_launch(void* const* d_in, const int* in_sizes, int n_in,
                              void* d_out, int out_size) {
    const float* x      = (const float*)d_in[0];
    const float* w_in   = (const float*)d_in[1];
    const float* b_in   = (const float*)d_in[2];
    const float* w_dw   = (const float*)d_in[3];
    const float* b_dw   = (const float*)d_in[4];
    const float* ln_g   = (const float*)d_in[5];
    const float* ln_b   = (const float*)d_in[6];
    const float* w_off  = (const float*)d_in[7];
    const float* b_off  = (const float*)d_in[8];
    const float* w_mask = (const float*)d_in[9];
    const float* b_mask = (const float*)d_in[10];
    const float* w_out  = (const float*)d_in[11];
    const float* b_out  = (const float*)d_in[12];
    const float* bn_g   = (const float*)d_in[13];
    const float* bn_b   = (const float*)d_in[14];
    const float* bn_m   = (const float*)d_in[15];
    const float* bn_v   = (const float*)d_in[16];

    // one-time setup (first call is the uncaptured correctness run)
    static int inited = 0;
    static cudaStream_t s1;
    static cudaEvent_t evS, evT, evP, ev2;
    if (!inited) {
        cudaFuncSetAttribute(gemm_in, cudaFuncAttributeMaxDynamicSharedMemorySize, TF_DSMEM);
        cudaFuncSetAttribute(gemm_om, cudaFuncAttributeMaxDynamicSharedMemorySize, TF_DSMEM);
        cudaFuncSetAttribute(gemm_out, cudaFuncAttributeMaxDynamicSharedMemorySize, TF_DSMEM);
        cudaStreamCreateWithFlags(&s1, cudaStreamNonBlocking);
        cudaEventCreateWithFlags(&evS, cudaEventDisableTiming);
        cudaEventCreateWithFlags(&evT, cudaEventDisableTiming);
        cudaEventCreateWithFlags(&evP, cudaEventDisableTiming);
        cudaEventCreateWithFlags(&ev2, cudaEventDisableTiming);
        inited = 1;
    }

    // fork s1 from the main (capture) stream
    cudaEventRecord(evS, 0);
    cudaStreamWaitEvent(s1, evS, 0);

    // s1: fused weight prep (independent of input transpose)
    prep_weights<<<3072, 256, 0, s1>>>(w_in, w_out, w_off, b_off, w_mask, b_mask);
    cudaEventRecord(evP, s1);

    // s0: NCHW -> NHWC (+ tf32 copy)
    nchw_to_nhwc<<<dim3(HW / 32, Cc / 32, Bn), dim3(32, 8)>>>(x);
    cudaEventRecord(evT, 0);

    // s1: depthwise branch + offset/mask GEMM (after transpose)
    cudaStreamWaitEvent(s1, evT, 0);
    dw_ln_gelu<<<Mtot / 8, 256, 0, s1>>>(w_dw, b_dw, ln_g, ln_b);
    gemm_om<<<dim3(NPAD / 128, Mtot / 128), 256, TF_DSMEM, s1>>>();
    cudaEventRecord(ev2, s1);

    // s0: input_proj (after weight prep) — overlaps with dw+gemm_om on s1
    cudaStreamWaitEvent(0, evP, 0);
    gemm_in<<<dim3(Cc / 128, Mtot / 128), 256, TF_DSMEM>>>(b_in);

    // join: dcn needs xp (s0) + om (s1)
    cudaStreamWaitEvent(0, ev2, 0);
    dcn_sample<<<(Mtot * Gg) / 8, 256>>>();
    // output_proj + BN + SiLU (tf32)
    gemm_out<<<dim3(Cc / 128, Mtot / 128), 256, TF_DSMEM>>>(b_out, bn_g, bn_b,
                                                            bn_m, bn_v, (float*)d_out);
}